// round 1
// baseline (speedup 1.0000x reference)
#include <cuda_runtime.h>
#include <cstdint>

#define NN   50000
#define EN   800000
#define DD   256
#define HH   8
#define CC   32
#define DE   64
#define NEG  0.2f

// ---------------- device scratch (allocation-free rule: __device__ globals) ----------------
__device__ float g_xl[(size_t)NN * DD];
__device__ float g_xr[(size_t)NN * DD];
__device__ float g_base[(size_t)NN * DD];
__device__ float g_w[(size_t)EN * HH];
__device__ float g_denom[(size_t)NN * HH];
__device__ int   g_counts[NN];
__device__ int   g_offsets[NN + 1];
__device__ int   g_cursor[NN];
__device__ int   g_csr[EN];

// ---------------- K0: zero denom + counts ----------------
__global__ void zero_kernel() {
    int i = blockIdx.x * blockDim.x + threadIdx.x;
    if (i < NN * HH) g_denom[i] = 0.f;
    if (i < NN) g_counts[i] = 0;
}

// ---------------- K1: node GEMMs: xl = x@Wl^T+bl, xr = x@Wr^T+br, base = x@Wres^T+bias ----
// C[m,o] = sum_k A[m,k]*W[o,k] + b[o].  64x64 tile, BK=32, 256 threads, 4x4 microtile.
__global__ __launch_bounds__(256) void node_gemm_kernel(
    const float* __restrict__ x,
    const float* __restrict__ Wl, const float* __restrict__ bl,
    const float* __restrict__ Wr, const float* __restrict__ br,
    const float* __restrict__ Wres, const float* __restrict__ bres)
{
    __shared__ __align__(16) float sA[32][68];
    __shared__ __align__(16) float sB[32][68];

    int tid = threadIdx.x;
    int tx = tid & 15;        // output-col group: o = o0 + tx*4 .. +3
    int ty = tid >> 4;        // row group: m = m0 + ty*4 .. +3
    int m0 = blockIdx.x * 64;
    int grp = blockIdx.y;     // 0..11
    int mat = grp >> 2;
    int o0 = (grp & 3) * 64;

    const float* W   = (mat == 0) ? Wl : ((mat == 1) ? Wr : Wres);
    const float* bv  = (mat == 0) ? bl : ((mat == 1) ? br : bres);
    float* out       = (mat == 0) ? g_xl : ((mat == 1) ? g_xr : g_base);

    float acc[4][4];
#pragma unroll
    for (int i = 0; i < 4; i++)
#pragma unroll
        for (int j = 0; j < 4; j++) acc[i][j] = 0.f;

    for (int kt = 0; kt < DD; kt += 32) {
#pragma unroll
        for (int j = 0; j < 2; j++) {
            int idx = tid + j * 256;
            int row = idx >> 3;
            int kq  = (idx & 7) << 2;
            int m = m0 + row; if (m >= NN) m = NN - 1;
            float4 va = __ldg((const float4*)(x + (size_t)m * DD + kt + kq));
            sA[kq + 0][row] = va.x; sA[kq + 1][row] = va.y;
            sA[kq + 2][row] = va.z; sA[kq + 3][row] = va.w;
            float4 vb = __ldg((const float4*)(W + (size_t)(o0 + row) * DD + kt + kq));
            sB[kq + 0][row] = vb.x; sB[kq + 1][row] = vb.y;
            sB[kq + 2][row] = vb.z; sB[kq + 3][row] = vb.w;
        }
        __syncthreads();
#pragma unroll
        for (int k = 0; k < 32; k++) {
            float4 a4 = *(const float4*)&sA[k][ty * 4];
            float4 b4 = *(const float4*)&sB[k][tx * 4];
            float av[4] = {a4.x, a4.y, a4.z, a4.w};
            float bw[4] = {b4.x, b4.y, b4.z, b4.w};
#pragma unroll
            for (int im = 0; im < 4; im++)
#pragma unroll
                for (int io = 0; io < 4; io++)
                    acc[im][io] += av[im] * bw[io];
        }
        __syncthreads();
    }

#pragma unroll
    for (int im = 0; im < 4; im++) {
        int m = m0 + ty * 4 + im;
        if (m < NN) {
            int oc = o0 + tx * 4;
            float4 r;
            r.x = acc[im][0] + __ldg(&bv[oc + 0]);
            r.y = acc[im][1] + __ldg(&bv[oc + 1]);
            r.z = acc[im][2] + __ldg(&bv[oc + 2]);
            r.w = acc[im][3] + __ldg(&bv[oc + 3]);
            *(float4*)(out + (size_t)m * DD + oc) = r;
        }
    }
}

// ---------------- K2: per-edge attention logits with fused ee GEMM ----------------
// Tile: 64 edges per block, 256 threads. Thread (tx,ty): channels o = tx*16..+15,
// edges e = ty*4..+3.  ee computed in registers from smem EA tile and smem W_e^T.
// Then alpha_h = sum_c att[h,c]*leaky(xl[src]+xr[dst]+ee); w = exp(alpha) (no max
// subtraction — |alpha| is O(1) by construction); atomicAdd into denom[dst,h].
#define K2_SMEM_FLOATS (64 * 260 + 64 * 68)
#define K2_SMEM_BYTES  (K2_SMEM_FLOATS * 4 + 128 * 4)

__global__ __launch_bounds__(256, 2) void edge_alpha_kernel(
    const float* __restrict__ edge_attr,
    const float* __restrict__ We,
    const float* __restrict__ att,
    const int* __restrict__ esrc,
    const int* __restrict__ edst)
{
    extern __shared__ float smem[];
    float* sW  = smem;                       // [64][260] : W_e^T  (k-major, padded)
    float* sEA = smem + 64 * 260;            // [64][68]  : edge_attr tile
    int*   sSrc = (int*)(smem + K2_SMEM_FLOATS);
    int*   sDst = sSrc + 64;

    int tid = threadIdx.x;
    int tx = tid & 15;
    int ty = tid >> 4;
    int e0 = blockIdx.x * 64;

    // stage W_e transposed: We[o][k] -> sW[k][o]
    for (int i = tid; i < (DD * DE) / 4; i += 256) {
        int o = i >> 4;
        int kq = (i & 15) << 2;
        float4 v = __ldg((const float4*)(We + (size_t)o * DE + kq));
        sW[(kq + 0) * 260 + o] = v.x;
        sW[(kq + 1) * 260 + o] = v.y;
        sW[(kq + 2) * 260 + o] = v.z;
        sW[(kq + 3) * 260 + o] = v.w;
    }
    // stage EA tile
    for (int i = tid; i < (64 * DE) / 4; i += 256) {
        int e = i >> 4;
        int kq = (i & 15) << 2;
        float4 v = __ldg((const float4*)(edge_attr + (size_t)(e0 + e) * DE + kq));
        *(float4*)&sEA[e * 68 + kq] = v;
    }
    if (tid < 64) {
        sSrc[tid] = esrc[e0 + tid];
        sDst[tid] = edst[e0 + tid];
    }
    __syncthreads();

    float acc[4][16];
#pragma unroll
    for (int i = 0; i < 4; i++)
#pragma unroll
        for (int j = 0; j < 16; j++) acc[i][j] = 0.f;

    const float* ea0 = &sEA[(ty * 4 + 0) * 68];
    const float* ea1 = &sEA[(ty * 4 + 1) * 68];
    const float* ea2 = &sEA[(ty * 4 + 2) * 68];
    const float* ea3 = &sEA[(ty * 4 + 3) * 68];

#pragma unroll 4
    for (int k = 0; k < DE; k++) {
        float a0 = ea0[k], a1 = ea1[k], a2 = ea2[k], a3 = ea3[k];
        const float* wk = sW + k * 260 + tx * 16;
        float4 b0 = *(const float4*)(wk);
        float4 b1 = *(const float4*)(wk + 4);
        float4 b2 = *(const float4*)(wk + 8);
        float4 b3 = *(const float4*)(wk + 12);
        float bb[16] = {b0.x, b0.y, b0.z, b0.w, b1.x, b1.y, b1.z, b1.w,
                        b2.x, b2.y, b2.z, b2.w, b3.x, b3.y, b3.z, b3.w};
#pragma unroll
        for (int c = 0; c < 16; c++) {
            acc[0][c] += a0 * bb[c];
            acc[1][c] += a1 * bb[c];
            acc[2][c] += a2 * bb[c];
            acc[3][c] += a3 * bb[c];
        }
    }

    int h = tx >> 1;
    float4 at0 = __ldg((const float4*)(att + tx * 16));
    float4 at1 = __ldg((const float4*)(att + tx * 16 + 4));
    float4 at2 = __ldg((const float4*)(att + tx * 16 + 8));
    float4 at3 = __ldg((const float4*)(att + tx * 16 + 12));
    float atv[16] = {at0.x, at0.y, at0.z, at0.w, at1.x, at1.y, at1.z, at1.w,
                     at2.x, at2.y, at2.z, at2.w, at3.x, at3.y, at3.z, at3.w};

#pragma unroll
    for (int je = 0; je < 4; je++) {
        int el = ty * 4 + je;
        int s = sSrc[el];
        int d = sDst[el];
        const float* xlp = g_xl + (size_t)s * DD + tx * 16;
        const float* xrp = g_xr + (size_t)d * DD + tx * 16;
        float p = 0.f;
#pragma unroll
        for (int q = 0; q < 4; q++) {
            float4 u = __ldg((const float4*)(xlp + q * 4));
            float4 r = __ldg((const float4*)(xrp + q * 4));
            float v0 = u.x + r.x + acc[je][q * 4 + 0]; v0 = (v0 > 0.f) ? v0 : NEG * v0;
            float v1 = u.y + r.y + acc[je][q * 4 + 1]; v1 = (v1 > 0.f) ? v1 : NEG * v1;
            float v2 = u.z + r.z + acc[je][q * 4 + 2]; v2 = (v2 > 0.f) ? v2 : NEG * v2;
            float v3 = u.w + r.w + acc[je][q * 4 + 3]; v3 = (v3 > 0.f) ? v3 : NEG * v3;
            p += v0 * atv[q * 4 + 0] + v1 * atv[q * 4 + 1]
               + v2 * atv[q * 4 + 2] + v3 * atv[q * 4 + 3];
        }
        p += __shfl_xor_sync(0xffffffffu, p, 1);
        if ((tx & 1) == 0) {
            float w = __expf(p);
            g_w[(size_t)(e0 + el) * HH + h] = w;
            atomicAdd(&g_denom[(size_t)d * HH + h], w);
        }
    }
}

// ---------------- K3: CSR build (histogram -> scan -> fill) ----------------
__global__ void hist_kernel(const int* __restrict__ edst) {
    int e = blockIdx.x * blockDim.x + threadIdx.x;
    if (e < EN) atomicAdd(&g_counts[edst[e]], 1);
}

__global__ void scan_kernel() {
    __shared__ int ss[1024];
    const int n = NN, chunk = 49;   // 1024*49 = 50176 >= 50000
    int tid = threadIdx.x;
    int start = tid * chunk;
    int end = start + chunk; if (end > n) end = n;
    int s = 0;
    for (int i = start; i < end && i < n; i++) s += g_counts[i];
    ss[tid] = s;
    __syncthreads();
    for (int off = 1; off < 1024; off <<= 1) {
        int t = (tid >= off) ? ss[tid - off] : 0;
        __syncthreads();
        ss[tid] += t;
        __syncthreads();
    }
    int run = ss[tid] - s;  // exclusive prefix
    for (int i = start; i < end && i < n; i++) {
        g_offsets[i] = run;
        run += g_counts[i];
    }
    if (start < n && end == n) g_offsets[n] = run;
}

__global__ void cursor_copy_kernel() {
    int i = blockIdx.x * blockDim.x + threadIdx.x;
    if (i < NN) g_cursor[i] = g_offsets[i];
}

__global__ void fill_kernel(const int* __restrict__ edst) {
    int e = blockIdx.x * blockDim.x + threadIdx.x;
    if (e < EN) {
        int d = edst[e];
        int p = atomicAdd(&g_cursor[d], 1);
        g_csr[p] = e;
    }
}

// ---------------- K4: per-node aggregation + residual + LayerNorm ----------------
__global__ __launch_bounds__(256) void aggregate_ln_kernel(
    const int* __restrict__ esrc,
    const float* __restrict__ gamma,
    const float* __restrict__ beta,
    float* __restrict__ out)
{
    int i = blockIdx.x;
    int tid = threadIdx.x;
    int h = tid >> 5;
    __shared__ float sinv[8];
    __shared__ float sred[8], sred2[8];

    if (tid < 8) {
        float d = g_denom[(size_t)i * HH + tid];
        sinv[tid] = 1.f / d;   // inf if no edges; never used in that case
    }
    __syncthreads();

    int p0 = g_offsets[i], p1 = g_offsets[i + 1];
    float inv = sinv[h];
    float acc = 0.f;
    for (int p = p0; p < p1; p++) {
        int e = g_csr[p];
        int s = __ldg(&esrc[e]);
        float w = __ldg(&g_w[(size_t)e * HH + h]);
        acc += __ldg(&g_xl[(size_t)s * DD + tid]) * (w * inv);
    }
    float v = acc + g_base[(size_t)i * DD + tid];

    float s1 = v, s2 = v * v;
#pragma unroll
    for (int off = 16; off; off >>= 1) {
        s1 += __shfl_down_sync(0xffffffffu, s1, off);
        s2 += __shfl_down_sync(0xffffffffu, s2, off);
    }
    if ((tid & 31) == 0) { sred[tid >> 5] = s1; sred2[tid >> 5] = s2; }
    __syncthreads();
    if (tid == 0) {
        float a = 0.f, b = 0.f;
#pragma unroll
        for (int j = 0; j < 8; j++) { a += sred[j]; b += sred2[j]; }
        float mu = a * (1.f / DD);
        float var = b * (1.f / DD) - mu * mu;
        sred[0] = mu;
        sred2[0] = rsqrtf(fmaxf(var, 0.f) + 1e-5f);
    }
    __syncthreads();
    float mu = sred[0], rstd = sred2[0];
    out[(size_t)i * DD + tid] = (v - mu) * rstd * __ldg(&gamma[tid]) + __ldg(&beta[tid]);
}

// ---------------- launch ----------------
extern "C" void kernel_launch(void* const* d_in, const int* in_sizes, int n_in,
                              void* d_out, int out_size)
{
    const float *x, *ea, *Wl, *bl, *Wr, *br, *We, *att, *Wres, *bias, *gamma, *beta;
    const int* eidx;

    if (n_in >= 13 && in_sizes[2] == 2 * EN) {
        // dict order: x, edge_attr, edge_index, W_l, b_l, W_r, b_r, W_e, att, W_res, bias, gamma, beta
        x     = (const float*)d_in[0];
        ea    = (const float*)d_in[1];
        eidx  = (const int*)  d_in[2];
        Wl    = (const float*)d_in[3];
        bl    = (const float*)d_in[4];
        Wr    = (const float*)d_in[5];
        br    = (const float*)d_in[6];
        We    = (const float*)d_in[7];
        att   = (const float*)d_in[8];
        Wres  = (const float*)d_in[9];
        bias  = (const float*)d_in[10];
        gamma = (const float*)d_in[11];
        beta  = (const float*)d_in[12];
    } else {
        // signature order: x, edge_attr, W_l, b_l, W_r, b_r, W_e, att, W_res, bias, gamma, beta, edge_index
        x     = (const float*)d_in[0];
        ea    = (const float*)d_in[1];
        Wl    = (const float*)d_in[2];
        bl    = (const float*)d_in[3];
        Wr    = (const float*)d_in[4];
        br    = (const float*)d_in[5];
        We    = (const float*)d_in[6];
        att   = (const float*)d_in[7];
        Wres  = (const float*)d_in[8];
        bias  = (const float*)d_in[9];
        gamma = (const float*)d_in[10];
        beta  = (const float*)d_in[11];
        eidx  = (const int*)  d_in[12];
    }
    const int* esrc = eidx;
    const int* edst = eidx + EN;
    float* out = (float*)d_out;

    cudaFuncSetAttribute(edge_alpha_kernel,
                         cudaFuncAttributeMaxDynamicSharedMemorySize, K2_SMEM_BYTES);

    zero_kernel<<<(NN * HH + 255) / 256, 256>>>();
    node_gemm_kernel<<<dim3((NN + 63) / 64, 12), 256>>>(x, Wl, bl, Wr, br, Wres, bias);
    edge_alpha_kernel<<<EN / 64, 256, K2_SMEM_BYTES>>>(ea, We, att, esrc, edst);
    hist_kernel<<<(EN + 255) / 256, 256>>>(edst);
    scan_kernel<<<1, 1024>>>();
    cursor_copy_kernel<<<(NN + 255) / 256, 256>>>();
    fill_kernel<<<(EN + 255) / 256, 256>>>(edst);
    aggregate_ln_kernel<<<NN, 256>>>(esrc, gamma, beta, out);
}

// round 5
// speedup vs baseline: 2.3792x; 2.3792x over previous
#include <cuda_runtime.h>
#include <cuda_bf16.h>
#include <cstdint>

#define NN   50000
#define EN   800000
#define DD   256
#define HH   8
#define DE   64
#define NEG  0.2f

// ---------------- device scratch ----------------
__device__ float g_xl[(size_t)NN * DD];
__device__ float g_xr[(size_t)NN * DD];
__device__ float g_base[(size_t)NN * DD];
__device__ float g_w[(size_t)EN * HH];
__device__ float g_denom[(size_t)NN * HH];
__device__ int   g_counts[NN];
__device__ int   g_offsets[NN + 1];
__device__ int   g_cursor[NN];
__device__ int   g_csr[EN];

// ---------------- helpers ----------------
__device__ __forceinline__ uint32_t s2u(const void* p) {
    uint32_t a;
    asm("{ .reg .u64 t; cvta.to.shared.u64 t, %1; cvt.u32.u64 %0, t; }" : "=r"(a) : "l"(p));
    return a;
}
__device__ __forceinline__ void ldsm_x4(uint32_t* r, uint32_t addr) {
    asm volatile("ldmatrix.sync.aligned.m8n8.x4.shared.b16 {%0,%1,%2,%3}, [%4];"
        : "=r"(r[0]), "=r"(r[1]), "=r"(r[2]), "=r"(r[3]) : "r"(addr));
}
__device__ __forceinline__ void mma16816(float* c, const uint32_t* a, uint32_t b0, uint32_t b1) {
    asm volatile("mma.sync.aligned.m16n8k16.row.col.f32.bf16.bf16.f32 "
        "{%0,%1,%2,%3}, {%4,%5,%6,%7}, {%8,%9}, {%0,%1,%2,%3};"
        : "+f"(c[0]), "+f"(c[1]), "+f"(c[2]), "+f"(c[3])
        : "r"(a[0]), "r"(a[1]), "r"(a[2]), "r"(a[3]), "r"(b0), "r"(b1));
}
// pack 4 floats to 4 bf16 (hi or residual-lo part)
__device__ __forceinline__ uint2 pack4(float4 v, bool lo) {
    __nv_bfloat16 h0 = __float2bfloat16(v.x), h1 = __float2bfloat16(v.y);
    __nv_bfloat16 h2 = __float2bfloat16(v.z), h3 = __float2bfloat16(v.w);
    if (lo) {
        h0 = __float2bfloat16(v.x - __bfloat162float(h0));
        h1 = __float2bfloat16(v.y - __bfloat162float(h1));
        h2 = __float2bfloat16(v.z - __bfloat162float(h2));
        h3 = __float2bfloat16(v.w - __bfloat162float(h3));
    }
    uint2 r;
    r.x = ((uint32_t)__bfloat16_as_ushort(h1) << 16) | __bfloat16_as_ushort(h0);
    r.y = ((uint32_t)__bfloat16_as_ushort(h3) << 16) | __bfloat16_as_ushort(h2);
    return r;
}
__device__ __forceinline__ uint32_t bfpack2(float a, float b) {
    __nv_bfloat162 h;
    h.x = __float2bfloat16(a);
    h.y = __float2bfloat16(b);
    return *(uint32_t*)&h;
}
__device__ __forceinline__ float2 unpk(uint32_t u) {
    __nv_bfloat162 h = *(__nv_bfloat162*)&u;
    return __bfloat1622float2(h);
}

// fragment address helpers (pitch 40 bf16 per row; base = byte addr of tile)
__device__ __forceinline__ uint32_t a_frag_addr(uint32_t base, int mrow0, int kk, int lane) {
    int row = mrow0 + (lane & 15);
    int col = kk + ((lane >> 4) << 3);
    return base + (uint32_t)(row * 40 + col) * 2;
}
__device__ __forceinline__ uint32_t b_frag_addr(uint32_t base, int n0, int kk, int lane) {
    int row = n0 + (lane & 7) + ((lane >> 4) << 3);
    int col = kk + (((lane >> 3) & 1) << 3);
    return base + (uint32_t)(row * 40 + col) * 2;
}

// run 3 split passes (AhBh, AlBh, AhBl) for one 32-wide K chunk.
// acc[2][8][4]: warp tile 32x64 = 2 m16 x 8 n8.
__device__ __forceinline__ void mma_chunk(
    float acc[2][8][4],
    uint32_t aHi, uint32_t aLo, uint32_t bHi, uint32_t bLo,
    int mwarp, int nwarp, int lane)
{
#pragma unroll
    for (int p = 0; p < 3; p++) {
        uint32_t ab = (p == 1) ? aLo : aHi;
        uint32_t bb = (p == 2) ? bLo : bHi;
#pragma unroll
        for (int ks = 0; ks < 32; ks += 16) {
            uint32_t af[2][4];
            ldsm_x4(af[0], a_frag_addr(ab, mwarp * 32, ks, lane));
            ldsm_x4(af[1], a_frag_addr(ab, mwarp * 32 + 16, ks, lane));
#pragma unroll
            for (int ng = 0; ng < 4; ng++) {
                uint32_t bf[4];
                ldsm_x4(bf, b_frag_addr(bb, nwarp * 64 + ng * 16, ks, lane));
                mma16816(acc[0][2 * ng + 0], af[0], bf[0], bf[1]);
                mma16816(acc[0][2 * ng + 1], af[0], bf[2], bf[3]);
                mma16816(acc[1][2 * ng + 0], af[1], bf[0], bf[1]);
                mma16816(acc[1][2 * ng + 1], af[1], bf[2], bf[3]);
            }
        }
    }
}

// ---------------- K0: zero ----------------
__global__ void zero_kernel() {
    int i = blockIdx.x * blockDim.x + threadIdx.x;
    if (i < NN * HH) g_denom[i] = 0.f;
    if (i < NN) g_counts[i] = 0;
}

// ---------------- node GEMM (HMMA): out = x @ W^T + b ----------------
// grid: (ceil(NN/128), 6): blockIdx.y -> mat(3) x nhalf(2). Block 128x128 tile.
#define NA_HI 0u
#define NA_LO 10240u
#define NB_HI 20480u
#define NB_LO 30720u
#define NODE_SMEM 40960

__global__ __launch_bounds__(256, 1) void node_gemm_tc(
    const float* __restrict__ x,
    const float* __restrict__ Wl, const float* __restrict__ bl,
    const float* __restrict__ Wr, const float* __restrict__ br,
    const float* __restrict__ Wres, const float* __restrict__ bres)
{
    extern __shared__ char smem[];
    uint32_t sb = s2u(smem);
    int tid = threadIdx.x, lane = tid & 31, wid = tid >> 5;
    int mwarp = wid >> 1, nwarp = wid & 1;
    int m0 = blockIdx.x * 128;
    int mat = blockIdx.y >> 1;
    int nhalf = blockIdx.y & 1;

    const float* W  = (mat == 0) ? Wl : ((mat == 1) ? Wr : Wres);
    const float* bv = (mat == 0) ? bl : ((mat == 1) ? br : bres);
    float* out      = (mat == 0) ? g_xl : ((mat == 1) ? g_xr : g_base);
    int ncol0 = nhalf * 128;

    float acc[2][8][4];
#pragma unroll
    for (int i = 0; i < 2; i++)
#pragma unroll
        for (int j = 0; j < 8; j++)
#pragma unroll
            for (int k = 0; k < 4; k++) acc[i][j][k] = 0.f;

    for (int c = 0; c < 8; c++) {
        int k0 = c * 32;
        __syncthreads();
        // stage A: 128x32 fp32 -> hi/lo bf16
#pragma unroll
        for (int it = 0; it < 4; it++) {
            int i = tid + it * 256;           // 0..1023 float4s
            int r = i >> 3, kq = (i & 7) << 2;
            int m = m0 + r; if (m >= NN) m = NN - 1;
            float4 v = __ldg((const float4*)(x + (size_t)m * DD + k0 + kq));
            uint32_t off = (uint32_t)(r * 40 + kq) * 2;
            *(uint2*)(smem + NA_HI + off) = pack4(v, false);
            *(uint2*)(smem + NA_LO + off) = pack4(v, true);
        }
        // stage B: 128x32
#pragma unroll
        for (int it = 0; it < 4; it++) {
            int i = tid + it * 256;
            int r = i >> 3, kq = (i & 7) << 2;
            float4 v = __ldg((const float4*)(W + (size_t)(ncol0 + r) * DD + k0 + kq));
            uint32_t off = (uint32_t)(r * 40 + kq) * 2;
            *(uint2*)(smem + NB_HI + off) = pack4(v, false);
            *(uint2*)(smem + NB_LO + off) = pack4(v, true);
        }
        __syncthreads();
        mma_chunk(acc, sb + NA_HI, sb + NA_LO, sb + NB_HI, sb + NB_LO, mwarp, nwarp, lane);
    }

    // epilogue: add bias, store fp32
#pragma unroll
    for (int mt = 0; mt < 2; mt++) {
        int row = m0 + mwarp * 32 + mt * 16 + (lane >> 2);
#pragma unroll
        for (int nt = 0; nt < 8; nt++) {
            int col = ncol0 + nwarp * 64 + nt * 8 + ((lane & 3) << 1);
            float b0 = __ldg(&bv[col]), b1 = __ldg(&bv[col + 1]);
            if (row < NN) {
                float2 v = {acc[mt][nt][0] + b0, acc[mt][nt][1] + b1};
                *(float2*)(out + (size_t)row * DD + col) = v;
            }
            if (row + 8 < NN) {
                float2 v = {acc[mt][nt][2] + b0, acc[mt][nt][3] + b1};
                *(float2*)(out + (size_t)(row + 8) * DD + col) = v;
            }
        }
    }
}

// ---------------- edge kernel: fused ee GEMM (HMMA) + attention logits ----------------
// Block = 128 edges, 256 threads. ee[128x256] kept in smem bf16 (pitch 133 words).
#define EE_OFF  0u
#define EA_HI   68096u             // 2 chunks x 128 x 40 bf16 = 20480
#define EA_LO   (EA_HI + 20480u)
#define EB_HI   (EA_LO + 20480u)   // 128 x 40 bf16 = 10240
#define EB_LO   (EB_HI + 10240u)
#define EIDX    (EB_LO + 10240u)
#define EDGE_SMEM (EIDX + 1024u)

__global__ __launch_bounds__(256, 1) void edge_kernel_tc(
    const float* __restrict__ ea,
    const float* __restrict__ We,
    const float* __restrict__ att,
    const int* __restrict__ esrc,
    const int* __restrict__ edst)
{
    extern __shared__ char smem[];
    uint32_t sb = s2u(smem);
    int tid = threadIdx.x, lane = tid & 31, wid = tid >> 5;
    int mwarp = wid >> 1, nwarp = wid & 1;
    int e0 = blockIdx.x * 128;
    int* sSrc = (int*)(smem + EIDX);
    int* sDst = sSrc + 128;
    uint32_t* ee32 = (uint32_t*)(smem + EE_OFF);

    if (tid < 128) { sSrc[tid] = esrc[e0 + tid]; sDst[tid] = edst[e0 + tid]; }

    // stage A (edge_attr 128x64, both 32-chunks) hi + lo
#pragma unroll
    for (int it = 0; it < 8; it++) {
        int i = tid + it * 256;                // 0..2047 float4s
        int r = i >> 4, kq = (i & 15) << 2;    // kq 0..60
        float4 v = __ldg((const float4*)(ea + (size_t)(e0 + r) * DE + kq));
        int ch = kq >> 5, kc = kq & 31;
        uint32_t off = (uint32_t)(ch * 5120 + r * 40 + kc) * 2;
        *(uint2*)(smem + EA_HI + off) = pack4(v, false);
        *(uint2*)(smem + EA_LO + off) = pack4(v, true);
    }

    for (int nh = 0; nh < 2; nh++) {
        float acc[2][8][4];
#pragma unroll
        for (int i = 0; i < 2; i++)
#pragma unroll
            for (int j = 0; j < 8; j++)
#pragma unroll
                for (int k = 0; k < 4; k++) acc[i][j][k] = 0.f;

        for (int c = 0; c < 2; c++) {
            __syncthreads();
            // stage B: We rows [nh*128 .. +127], cols c*32..+31
#pragma unroll
            for (int it = 0; it < 4; it++) {
                int i = tid + it * 256;
                int r = i >> 3, kq = (i & 7) << 2;
                float4 v = __ldg((const float4*)(We + (size_t)(nh * 128 + r) * DE + c * 32 + kq));
                uint32_t off = (uint32_t)(r * 40 + kq) * 2;
                *(uint2*)(smem + EB_HI + off) = pack4(v, false);
                *(uint2*)(smem + EB_LO + off) = pack4(v, true);
            }
            __syncthreads();
            mma_chunk(acc, sb + EA_HI + c * 10240, sb + EA_LO + c * 10240,
                      sb + EB_HI, sb + EB_LO, mwarp, nwarp, lane);
        }

        // dump acc -> ee smem bf16 (pitch 133 u32 words per edge)
#pragma unroll
        for (int mt = 0; mt < 2; mt++) {
            int el = mwarp * 32 + mt * 16 + (lane >> 2);
#pragma unroll
            for (int nt = 0; nt < 8; nt++) {
                int w = nh * 64 + nwarp * 32 + nt * 4 + (lane & 3);
                ee32[el * 133 + w]       = bfpack2(acc[mt][nt][0], acc[mt][nt][1]);
                ee32[(el + 8) * 133 + w] = bfpack2(acc[mt][nt][2], acc[mt][nt][3]);
            }
        }
    }
    __syncthreads();

    // logit phase: quad of lanes per edge, coalesced gathers
    int q = tid & 3;
    for (int rep = 0; rep < 2; rep++) {
        int el = (tid >> 2) + rep * 64;
        int s = sSrc[el];
        int d = sDst[el];
        const float* xlp = g_xl + (size_t)s * DD;
        const float* xrp = g_xr + (size_t)d * DD;
        uint32_t eeb = el * 133 + q * 4;
#pragma unroll
        for (int h = 0; h < 8; h++) {
            int cb = h * 32 + q * 8;
            float4 u0 = __ldg((const float4*)(xlp + cb));
            float4 u1 = __ldg((const float4*)(xlp + cb + 4));
            float4 r0 = __ldg((const float4*)(xrp + cb));
            float4 r1 = __ldg((const float4*)(xrp + cb + 4));
            float2 f0 = unpk(ee32[eeb + h * 16 + 0]);
            float2 f1 = unpk(ee32[eeb + h * 16 + 1]);
            float2 f2 = unpk(ee32[eeb + h * 16 + 2]);
            float2 f3 = unpk(ee32[eeb + h * 16 + 3]);
            float4 a0 = __ldg((const float4*)(att + cb));
            float4 a1 = __ldg((const float4*)(att + cb + 4));
            float p = 0.f, z;
            z = u0.x + r0.x + f0.x; z = (z > 0.f) ? z : NEG * z; p += z * a0.x;
            z = u0.y + r0.y + f0.y; z = (z > 0.f) ? z : NEG * z; p += z * a0.y;
            z = u0.z + r0.z + f1.x; z = (z > 0.f) ? z : NEG * z; p += z * a0.z;
            z = u0.w + r0.w + f1.y; z = (z > 0.f) ? z : NEG * z; p += z * a0.w;
            z = u1.x + r1.x + f2.x; z = (z > 0.f) ? z : NEG * z; p += z * a1.x;
            z = u1.y + r1.y + f2.y; z = (z > 0.f) ? z : NEG * z; p += z * a1.y;
            z = u1.z + r1.z + f3.x; z = (z > 0.f) ? z : NEG * z; p += z * a1.z;
            z = u1.w + r1.w + f3.y; z = (z > 0.f) ? z : NEG * z; p += z * a1.w;
            p += __shfl_xor_sync(0xffffffffu, p, 1);
            p += __shfl_xor_sync(0xffffffffu, p, 2);
            if (q == 0) {
                float w = __expf(p);
                g_w[(size_t)(e0 + el) * HH + h] = w;
                atomicAdd(&g_denom[(size_t)d * HH + h], w);
            }
        }
    }
}

// ---------------- CSR build ----------------
__global__ void hist_kernel(const int* __restrict__ edst) {
    int e = blockIdx.x * blockDim.x + threadIdx.x;
    if (e < EN) atomicAdd(&g_counts[edst[e]], 1);
}

__global__ void scan_kernel() {
    __shared__ int ss[1024];
    const int n = NN, chunk = 49;
    int tid = threadIdx.x;
    int start = tid * chunk;
    int end = start + chunk; if (end > n) end = n;
    int s = 0;
    for (int i = start; i < end && i < n; i++) s += g_counts[i];
    ss[tid] = s;
    __syncthreads();
    for (int off = 1; off < 1024; off <<= 1) {
        int t = (tid >= off) ? ss[tid - off] : 0;
        __syncthreads();
        ss[tid] += t;
        __syncthreads();
    }
    int run = ss[tid] - s;
    for (int i = start; i < end && i < n; i++) {
        g_offsets[i] = run;
        run += g_counts[i];
    }
    if (start < n && end == n) g_offsets[n] = run;
}

__global__ void cursor_copy_kernel() {
    int i = blockIdx.x * blockDim.x + threadIdx.x;
    if (i < NN) g_cursor[i] = g_offsets[i];
}

__global__ void fill_kernel(const int* __restrict__ edst) {
    int e = blockIdx.x * blockDim.x + threadIdx.x;
    if (e < EN) {
        int d = edst[e];
        int p = atomicAdd(&g_cursor[d], 1);
        g_csr[p] = e;
    }
}

// ---------------- aggregation + residual + LayerNorm ----------------
__global__ __launch_bounds__(256) void aggregate_ln_kernel(
    const int* __restrict__ esrc,
    const float* __restrict__ gamma,
    const float* __restrict__ beta,
    float* __restrict__ out)
{
    int i = blockIdx.x;
    int tid = threadIdx.x;
    int h = tid >> 5;
    __shared__ float sinv[8];
    __shared__ float sred[8], sred2[8];

    if (tid < 8) {
        float d = g_denom[(size_t)i * HH + tid];
        sinv[tid] = 1.f / d;
    }
    __syncthreads();

    int p0 = g_offsets[i], p1 = g_offsets[i + 1];
    float inv = sinv[h];
    float acc = 0.f;
    for (int p = p0; p < p1; p++) {
        int e = g_csr[p];
        int s = __ldg(&esrc[e]);
        float w = __ldg(&g_w[(size_t)e * HH + h]);
        acc += __ldg(&g_xl[(size_t)s * DD + tid]) * (w * inv);
    }
    float v = acc + g_base[(size_t)i * DD + tid];

    float s1 = v, s2 = v * v;
#pragma unroll
    for (int off = 16; off; off >>= 1) {
        s1 += __shfl_down_sync(0xffffffffu, s1, off);
        s2 += __shfl_down_sync(0xffffffffu, s2, off);
    }
    if ((tid & 31) == 0) { sred[tid >> 5] = s1; sred2[tid >> 5] = s2; }
    __syncthreads();
    if (tid == 0) {
        float a = 0.f, b = 0.f;
#pragma unroll
        for (int j = 0; j < 8; j++) { a += sred[j]; b += sred2[j]; }
        float mu = a * (1.f / DD);
        float var = b * (1.f / DD) - mu * mu;
        sred[0] = mu;
        sred2[0] = rsqrtf(fmaxf(var, 0.f) + 1e-5f);
    }
    __syncthreads();
    float mu = sred[0], rstd = sred2[0];
    out[(size_t)i * DD + tid] = (v - mu) * rstd * __ldg(&gamma[tid]) + __ldg(&beta[tid]);
}

// ---------------- launch ----------------
extern "C" void kernel_launch(void* const* d_in, const int* in_sizes, int n_in,
                              void* d_out, int out_size)
{
    const float *x, *ea, *Wl, *bl, *Wr, *br, *We, *att, *Wres, *bias, *gamma, *beta;
    const int* eidx;

    if (n_in >= 13 && in_sizes[2] == 2 * EN) {
        x     = (const float*)d_in[0];
        ea    = (const float*)d_in[1];
        eidx  = (const int*)  d_in[2];
        Wl    = (const float*)d_in[3];
        bl    = (const float*)d_in[4];
        Wr    = (const float*)d_in[5];
        br    = (const float*)d_in[6];
        We    = (const float*)d_in[7];
        att   = (const float*)d_in[8];
        Wres  = (const float*)d_in[9];
        bias  = (const float*)d_in[10];
        gamma = (const float*)d_in[11];
        beta  = (const float*)d_in[12];
    } else {
        x     = (const float*)d_in[0];
        ea    = (const float*)d_in[1];
        Wl    = (const float*)d_in[2];
        bl    = (const float*)d_in[3];
        Wr    = (const float*)d_in[4];
        br    = (const float*)d_in[5];
        We    = (const float*)d_in[6];
        att   = (const float*)d_in[7];
        Wres  = (const float*)d_in[8];
        bias  = (const float*)d_in[9];
        gamma = (const float*)d_in[10];
        beta  = (const float*)d_in[11];
        eidx  = (const int*)  d_in[12];
    }
    const int* esrc = eidx;
    const int* edst = eidx + EN;
    float* out = (float*)d_out;

    cudaFuncSetAttribute(node_gemm_tc, cudaFuncAttributeMaxDynamicSharedMemorySize, NODE_SMEM);
    cudaFuncSetAttribute(edge_kernel_tc, cudaFuncAttributeMaxDynamicSharedMemorySize, EDGE_SMEM);

    zero_kernel<<<(NN * HH + 255) / 256, 256>>>();
    node_gemm_tc<<<dim3((NN + 127) / 128, 6), 256, NODE_SMEM>>>(x, Wl, bl, Wr, br, Wres, bias);
    edge_kernel_tc<<<EN / 128, 256, EDGE_SMEM>>>(ea, We, att, esrc, edst);
    hist_kernel<<<(EN + 255) / 256, 256>>>(edst);
    scan_kernel<<<1, 1024>>>();
    cursor_copy_kernel<<<(NN + 255) / 256, 256>>>();
    fill_kernel<<<(EN + 255) / 256, 256>>>(edst);
    aggregate_ln_kernel<<<NN, 256>>>(esrc, gamma, beta, out);
}

// round 8
// speedup vs baseline: 2.8272x; 1.1883x over previous
#include <cuda_runtime.h>
#include <cuda_bf16.h>
#include <cstdint>

#define NN   50000
#define EN   800000
#define DD   256
#define HH   8
#define DE   64
#define NEG  0.2f

// ---------------- device scratch ----------------
__device__ float g_xl[(size_t)NN * DD];
__device__ float g_xr[(size_t)NN * DD];
__device__ float g_base[(size_t)NN * DD];
__device__ float g_w[(size_t)EN * HH];
__device__ float g_denom[(size_t)NN * HH];
__device__ int   g_counts[NN];
__device__ int   g_offsets[NN + 1];
__device__ int   g_cursor[NN];
__device__ int   g_csr[EN];

// ---------------- helpers ----------------
__device__ __forceinline__ uint32_t s2u(const void* p) {
    uint32_t a;
    asm("{ .reg .u64 t; cvta.to.shared.u64 t, %1; cvt.u32.u64 %0, t; }" : "=r"(a) : "l"(p));
    return a;
}
__device__ __forceinline__ void ldsm_x4(uint32_t* r, uint32_t addr) {
    asm volatile("ldmatrix.sync.aligned.m8n8.x4.shared.b16 {%0,%1,%2,%3}, [%4];"
        : "=r"(r[0]), "=r"(r[1]), "=r"(r[2]), "=r"(r[3]) : "r"(addr));
}
__device__ __forceinline__ void mma16816(float* c, const uint32_t* a, uint32_t b0, uint32_t b1) {
    asm volatile("mma.sync.aligned.m16n8k16.row.col.f32.bf16.bf16.f32 "
        "{%0,%1,%2,%3}, {%4,%5,%6,%7}, {%8,%9}, {%0,%1,%2,%3};"
        : "+f"(c[0]), "+f"(c[1]), "+f"(c[2]), "+f"(c[3])
        : "r"(a[0]), "r"(a[1]), "r"(a[2]), "r"(a[3]), "r"(b0), "r"(b1));
}
__device__ __forceinline__ uint2 pack4(float4 v, bool lo) {
    __nv_bfloat16 h0 = __float2bfloat16(v.x), h1 = __float2bfloat16(v.y);
    __nv_bfloat16 h2 = __float2bfloat16(v.z), h3 = __float2bfloat16(v.w);
    if (lo) {
        h0 = __float2bfloat16(v.x - __bfloat162float(h0));
        h1 = __float2bfloat16(v.y - __bfloat162float(h1));
        h2 = __float2bfloat16(v.z - __bfloat162float(h2));
        h3 = __float2bfloat16(v.w - __bfloat162float(h3));
    }
    uint2 r;
    r.x = ((uint32_t)__bfloat16_as_ushort(h1) << 16) | __bfloat16_as_ushort(h0);
    r.y = ((uint32_t)__bfloat16_as_ushort(h3) << 16) | __bfloat16_as_ushort(h2);
    return r;
}
__device__ __forceinline__ uint32_t bfpack2(float a, float b) {
    __nv_bfloat162 h;
    h.x = __float2bfloat16(a);
    h.y = __float2bfloat16(b);
    return *(uint32_t*)&h;
}
__device__ __forceinline__ float2 unpk(uint32_t u) {
    __nv_bfloat162 h = *(__nv_bfloat162*)&u;
    return __bfloat1622float2(h);
}

// fragment address helpers (pitch 40 bf16 per row; base = byte addr of tile)
__device__ __forceinline__ uint32_t a_frag_addr(uint32_t base, int mrow0, int kk, int lane) {
    int row = mrow0 + (lane & 15);
    int col = kk + ((lane >> 4) << 3);
    return base + (uint32_t)(row * 40 + col) * 2;
}
__device__ __forceinline__ uint32_t b_frag_addr(uint32_t base, int n0, int kk, int lane) {
    int row = n0 + (lane & 7) + ((lane >> 4) << 3);
    int col = kk + (((lane >> 3) & 1) << 3);
    return base + (uint32_t)(row * 40 + col) * 2;
}

// single-pass K=32 chunk
__device__ __forceinline__ void mma_chunk1(
    float acc[2][8][4], uint32_t ab, uint32_t bb, int mwarp, int nwarp, int lane)
{
#pragma unroll
    for (int ks = 0; ks < 32; ks += 16) {
        uint32_t af[2][4];
        ldsm_x4(af[0], a_frag_addr(ab, mwarp * 32, ks, lane));
        ldsm_x4(af[1], a_frag_addr(ab, mwarp * 32 + 16, ks, lane));
#pragma unroll
        for (int ng = 0; ng < 4; ng++) {
            uint32_t bf[4];
            ldsm_x4(bf, b_frag_addr(bb, nwarp * 64 + ng * 16, ks, lane));
            mma16816(acc[0][2 * ng + 0], af[0], bf[0], bf[1]);
            mma16816(acc[0][2 * ng + 1], af[0], bf[2], bf[3]);
            mma16816(acc[1][2 * ng + 0], af[1], bf[0], bf[1]);
            mma16816(acc[1][2 * ng + 1], af[1], bf[2], bf[3]);
        }
    }
}
// 3-pass split chunk (node GEMM precision path)
__device__ __forceinline__ void mma_chunk3(
    float acc[2][8][4],
    uint32_t aHi, uint32_t aLo, uint32_t bHi, uint32_t bLo,
    int mwarp, int nwarp, int lane)
{
    mma_chunk1(acc, aHi, bHi, mwarp, nwarp, lane);
    mma_chunk1(acc, aLo, bHi, mwarp, nwarp, lane);
    mma_chunk1(acc, aHi, bLo, mwarp, nwarp, lane);
}

// ---------------- K0: zero ----------------
__global__ void zero_kernel() {
    int i = blockIdx.x * blockDim.x + threadIdx.x;
    if (i < NN * HH) g_denom[i] = 0.f;
    if (i < NN) g_counts[i] = 0;
}

// ---------------- node GEMM (HMMA, 3-pass split): out = x @ W^T + b ----------------
#define NA_HI 0u
#define NA_LO 10240u
#define NB_HI 20480u
#define NB_LO 30720u
#define NODE_SMEM 40960

__global__ __launch_bounds__(256, 1) void node_gemm_tc(
    const float* __restrict__ x,
    const float* __restrict__ Wl, const float* __restrict__ bl,
    const float* __restrict__ Wr, const float* __restrict__ br,
    const float* __restrict__ Wres, const float* __restrict__ bres)
{
    extern __shared__ char smem[];
    uint32_t sb = s2u(smem);
    int tid = threadIdx.x, lane = tid & 31, wid = tid >> 5;
    int mwarp = wid >> 1, nwarp = wid & 1;
    int m0 = blockIdx.x * 128;
    int mat = blockIdx.y >> 1;
    int nhalf = blockIdx.y & 1;

    const float* W  = (mat == 0) ? Wl : ((mat == 1) ? Wr : Wres);
    const float* bv = (mat == 0) ? bl : ((mat == 1) ? br : bres);
    float* out      = (mat == 0) ? g_xl : ((mat == 1) ? g_xr : g_base);
    int ncol0 = nhalf * 128;

    float acc[2][8][4];
#pragma unroll
    for (int i = 0; i < 2; i++)
#pragma unroll
        for (int j = 0; j < 8; j++)
#pragma unroll
            for (int k = 0; k < 4; k++) acc[i][j][k] = 0.f;

    for (int c = 0; c < 8; c++) {
        int k0 = c * 32;
        __syncthreads();
#pragma unroll
        for (int it = 0; it < 4; it++) {
            int i = tid + it * 256;
            int r = i >> 3, kq = (i & 7) << 2;
            int m = m0 + r; if (m >= NN) m = NN - 1;
            float4 v = __ldg((const float4*)(x + (size_t)m * DD + k0 + kq));
            uint32_t off = (uint32_t)(r * 40 + kq) * 2;
            *(uint2*)(smem + NA_HI + off) = pack4(v, false);
            *(uint2*)(smem + NA_LO + off) = pack4(v, true);
        }
#pragma unroll
        for (int it = 0; it < 4; it++) {
            int i = tid + it * 256;
            int r = i >> 3, kq = (i & 7) << 2;
            float4 v = __ldg((const float4*)(W + (size_t)(ncol0 + r) * DD + k0 + kq));
            uint32_t off = (uint32_t)(r * 40 + kq) * 2;
            *(uint2*)(smem + NB_HI + off) = pack4(v, false);
            *(uint2*)(smem + NB_LO + off) = pack4(v, true);
        }
        __syncthreads();
        mma_chunk3(acc, sb + NA_HI, sb + NA_LO, sb + NB_HI, sb + NB_LO, mwarp, nwarp, lane);
    }

#pragma unroll
    for (int mt = 0; mt < 2; mt++) {
        int row = m0 + mwarp * 32 + mt * 16 + (lane >> 2);
#pragma unroll
        for (int nt = 0; nt < 8; nt++) {
            int col = ncol0 + nwarp * 64 + nt * 8 + ((lane & 3) << 1);
            float b0 = __ldg(&bv[col]), b1 = __ldg(&bv[col + 1]);
            if (row < NN) {
                float2 v = {acc[mt][nt][0] + b0, acc[mt][nt][1] + b1};
                *(float2*)(out + (size_t)row * DD + col) = v;
            }
            if (row + 8 < NN) {
                float2 v = {acc[mt][nt][2] + b0, acc[mt][nt][3] + b1};
                *(float2*)(out + (size_t)(row + 8) * DD + col) = v;
            }
        }
    }
}

// ---------------- edge kernel: fused ee GEMM (single-pass bf16) + logits + hist ----------------
#define EE_OFF  0u                  // 128 x 133 u32 = 68096 B
#define EA_OFF  68096u              // 2 chunks x 128 x 40 bf16 = 20480 B
#define EB_OFF  (EA_OFF + 20480u)   // 2 chunks x 128 x 40 bf16 = 20480 B
#define EIDX    (EB_OFF + 20480u)
#define EDGE_SMEM (EIDX + 1024u)    // 110080 -> 2 CTAs/SM

__global__ __launch_bounds__(256, 2) void edge_kernel_tc(
    const float* __restrict__ ea,
    const float* __restrict__ We,
    const float* __restrict__ att,
    const int* __restrict__ esrc,
    const int* __restrict__ edst)
{
    extern __shared__ char smem[];
    uint32_t sb = s2u(smem);
    int tid = threadIdx.x, lane = tid & 31, wid = tid >> 5;
    int mwarp = wid >> 1, nwarp = wid & 1;
    int e0 = blockIdx.x * 128;
    int* sSrc = (int*)(smem + EIDX);
    int* sDst = sSrc + 128;
    uint32_t* ee32 = (uint32_t*)(smem + EE_OFF);

    if (tid < 128) {
        int s = esrc[e0 + tid];
        int d = edst[e0 + tid];
        sSrc[tid] = s;
        sDst[tid] = d;
        atomicAdd(&g_counts[d], 1);   // fused histogram
    }

    // stage A (edge_attr 128x64) single-pass hi bf16
#pragma unroll
    for (int it = 0; it < 8; it++) {
        int i = tid + it * 256;
        int r = i >> 4, kq = (i & 15) << 2;
        float4 v = __ldg((const float4*)(ea + (size_t)(e0 + r) * DE + kq));
        int ch = kq >> 5, kc = kq & 31;
        uint32_t off = (uint32_t)(ch * 5120 + r * 40 + kc) * 2;
        *(uint2*)(smem + EA_OFF + off) = pack4(v, false);
    }

    for (int nh = 0; nh < 2; nh++) {
        if (nh) __syncthreads();   // previous mma reads of EB complete
        // stage B: We rows [nh*128 .. +127], full K=64 (both chunks)
#pragma unroll
        for (int it = 0; it < 8; it++) {
            int i = tid + it * 256;
            int r = i >> 4, kq = (i & 15) << 2;
            float4 v = __ldg((const float4*)(We + (size_t)(nh * 128 + r) * DE + kq));
            int ch = kq >> 5, kc = kq & 31;
            uint32_t off = (uint32_t)(ch * 5120 + r * 40 + kc) * 2;
            *(uint2*)(smem + EB_OFF + off) = pack4(v, false);
        }
        __syncthreads();

        float acc[2][8][4];
#pragma unroll
        for (int i = 0; i < 2; i++)
#pragma unroll
            for (int j = 0; j < 8; j++)
#pragma unroll
                for (int k = 0; k < 4; k++) acc[i][j][k] = 0.f;

#pragma unroll
        for (int c = 0; c < 2; c++)
            mma_chunk1(acc, sb + EA_OFF + c * 10240, sb + EB_OFF + c * 10240,
                       mwarp, nwarp, lane);

        // dump acc -> ee smem bf16 (pitch 133 u32 words per edge)
#pragma unroll
        for (int mt = 0; mt < 2; mt++) {
            int el = mwarp * 32 + mt * 16 + (lane >> 2);
#pragma unroll
            for (int nt = 0; nt < 8; nt++) {
                int w = nh * 64 + nwarp * 32 + nt * 4 + (lane & 3);
                ee32[el * 133 + w]       = bfpack2(acc[mt][nt][0], acc[mt][nt][1]);
                ee32[(el + 8) * 133 + w] = bfpack2(acc[mt][nt][2], acc[mt][nt][3]);
            }
        }
    }
    __syncthreads();

    // logit phase: quad of lanes per edge, coalesced gathers
    int q = tid & 3;
    for (int rep = 0; rep < 2; rep++) {
        int el = (tid >> 2) + rep * 64;
        int s = sSrc[el];
        int d = sDst[el];
        const float* xlp = g_xl + (size_t)s * DD;
        const float* xrp = g_xr + (size_t)d * DD;
        uint32_t eeb = el * 133 + q * 4;
#pragma unroll
        for (int h = 0; h < 8; h++) {
            int cb = h * 32 + q * 8;
            float4 u0 = __ldg((const float4*)(xlp + cb));
            float4 u1 = __ldg((const float4*)(xlp + cb + 4));
            float4 r0 = __ldg((const float4*)(xrp + cb));
            float4 r1 = __ldg((const float4*)(xrp + cb + 4));
            float2 f0 = unpk(ee32[eeb + h * 16 + 0]);
            float2 f1 = unpk(ee32[eeb + h * 16 + 1]);
            float2 f2 = unpk(ee32[eeb + h * 16 + 2]);
            float2 f3 = unpk(ee32[eeb + h * 16 + 3]);
            float4 a0 = __ldg((const float4*)(att + cb));
            float4 a1 = __ldg((const float4*)(att + cb + 4));
            float p = 0.f, z;
            z = u0.x + r0.x + f0.x; z = (z > 0.f) ? z : NEG * z; p += z * a0.x;
            z = u0.y + r0.y + f0.y; z = (z > 0.f) ? z : NEG * z; p += z * a0.y;
            z = u0.z + r0.z + f1.x; z = (z > 0.f) ? z : NEG * z; p += z * a0.z;
            z = u0.w + r0.w + f1.y; z = (z > 0.f) ? z : NEG * z; p += z * a0.w;
            z = u1.x + r1.x + f2.x; z = (z > 0.f) ? z : NEG * z; p += z * a1.x;
            z = u1.y + r1.y + f2.y; z = (z > 0.f) ? z : NEG * z; p += z * a1.y;
            z = u1.z + r1.z + f3.x; z = (z > 0.f) ? z : NEG * z; p += z * a1.z;
            z = u1.w + r1.w + f3.y; z = (z > 0.f) ? z : NEG * z; p += z * a1.w;
            p += __shfl_xor_sync(0xffffffffu, p, 1);
            p += __shfl_xor_sync(0xffffffffu, p, 2);
            if (q == 0) {
                float w = __expf(p);
                g_w[(size_t)(e0 + el) * HH + h] = w;
                atomicAdd(&g_denom[(size_t)d * HH + h], w);
            }
        }
    }
}

// ---------------- scan (also writes cursor) ----------------
__global__ void scan_kernel() {
    __shared__ int ss[1024];
    const int n = NN, chunk = 49;
    int tid = threadIdx.x;
    int start = tid * chunk;
    int end = start + chunk; if (end > n) end = n;
    int s = 0;
    for (int i = start; i < end && i < n; i++) s += g_counts[i];
    ss[tid] = s;
    __syncthreads();
    for (int off = 1; off < 1024; off <<= 1) {
        int t = (tid >= off) ? ss[tid - off] : 0;
        __syncthreads();
        ss[tid] += t;
        __syncthreads();
    }
    int run = ss[tid] - s;
    for (int i = start; i < end && i < n; i++) {
        g_offsets[i] = run;
        g_cursor[i] = run;
        run += g_counts[i];
    }
    if (start < n && end == n) g_offsets[n] = run;
}

__global__ void fill_kernel(const int* __restrict__ edst) {
    int e = blockIdx.x * blockDim.x + threadIdx.x;
    if (e < EN) {
        int d = edst[e];
        int p = atomicAdd(&g_cursor[d], 1);
        g_csr[p] = e;
    }
}

// ---------------- aggregation + residual + LayerNorm (stage-then-stream) ----------------
__global__ __launch_bounds__(256) void aggregate_ln_kernel(
    const int* __restrict__ esrc,
    const float* __restrict__ gamma,
    const float* __restrict__ beta,
    float* __restrict__ out)
{
    int i = blockIdx.x;
    int tid = threadIdx.x;
    int h = tid >> 5;
    __shared__ int   ssrc[64];
    __shared__ float sw[64 * 8];
    __shared__ float sred[8], sred2[8];

    int p0 = g_offsets[i], p1 = g_offsets[i + 1];
    float acc = 0.f;

    for (int base = p0; base < p1; base += 64) {
        int n = min(64, p1 - base);
        __syncthreads();
        if (tid < n) {
            int e = __ldg(&g_csr[base + tid]);
            ssrc[tid] = __ldg(&esrc[e]);
            const float* wp = g_w + (size_t)e * HH;
            float4 w0 = __ldg((const float4*)wp);
            float4 w1 = __ldg((const float4*)(wp + 4));
            *(float4*)&sw[tid * 8]     = w0;
            *(float4*)&sw[tid * 8 + 4] = w1;
        }
        __syncthreads();
        int j = 0;
        for (; j + 4 <= n; j += 4) {
            int s0 = ssrc[j], s1 = ssrc[j + 1], s2 = ssrc[j + 2], s3 = ssrc[j + 3];
            float w0 = sw[j * 8 + h], w1 = sw[(j + 1) * 8 + h];
            float w2 = sw[(j + 2) * 8 + h], w3 = sw[(j + 3) * 8 + h];
            float x0 = __ldg(&g_xl[(size_t)s0 * DD + tid]);
            float x1 = __ldg(&g_xl[(size_t)s1 * DD + tid]);
            float x2 = __ldg(&g_xl[(size_t)s2 * DD + tid]);
            float x3 = __ldg(&g_xl[(size_t)s3 * DD + tid]);
            acc += x0 * w0;
            acc += x1 * w1;
            acc += x2 * w2;
            acc += x3 * w3;
        }
        for (; j < n; j++)
            acc += __ldg(&g_xl[(size_t)ssrc[j] * DD + tid]) * sw[j * 8 + h];
    }

    float den = __ldg(&g_denom[(size_t)i * HH + h]);
    float invd = (den > 0.f) ? (1.f / den) : 0.f;
    float v = acc * invd + g_base[(size_t)i * DD + tid];

    float s1 = v, s2 = v * v;
#pragma unroll
    for (int off = 16; off; off >>= 1) {
        s1 += __shfl_down_sync(0xffffffffu, s1, off);
        s2 += __shfl_down_sync(0xffffffffu, s2, off);
    }
    if ((tid & 31) == 0) { sred[tid >> 5] = s1; sred2[tid >> 5] = s2; }
    __syncthreads();
    if (tid == 0) {
        float a = 0.f, b = 0.f;
#pragma unroll
        for (int j = 0; j < 8; j++) { a += sred[j]; b += sred2[j]; }
        float mu = a * (1.f / DD);
        float var = b * (1.f / DD) - mu * mu;
        sred[0] = mu;
        sred2[0] = rsqrtf(fmaxf(var, 0.f) + 1e-5f);
    }
    __syncthreads();
    float mu = sred[0], rstd = sred2[0];
    out[(size_t)i * DD + tid] = (v - mu) * rstd * __ldg(&gamma[tid]) + __ldg(&beta[tid]);
}

// ---------------- launch ----------------
extern "C" void kernel_launch(void* const* d_in, const int* in_sizes, int n_in,
                              void* d_out, int out_size)
{
    const float *x, *ea, *Wl, *bl, *Wr, *br, *We, *att, *Wres, *bias, *gamma, *beta;
    const int* eidx;

    if (n_in >= 13 && in_sizes[2] == 2 * EN) {
        x     = (const float*)d_in[0];
        ea    = (const float*)d_in[1];
        eidx  = (const int*)  d_in[2];
        Wl    = (const float*)d_in[3];
        bl    = (const float*)d_in[4];
        Wr    = (const float*)d_in[5];
        br    = (const float*)d_in[6];
        We    = (const float*)d_in[7];
        att   = (const float*)d_in[8];
        Wres  = (const float*)d_in[9];
        bias  = (const float*)d_in[10];
        gamma = (const float*)d_in[11];
        beta  = (const float*)d_in[12];
    } else {
        x     = (const float*)d_in[0];
        ea    = (const float*)d_in[1];
        Wl    = (const float*)d_in[2];
        bl    = (const float*)d_in[3];
        Wr    = (const float*)d_in[4];
        br    = (const float*)d_in[5];
        We    = (const float*)d_in[6];
        att   = (const float*)d_in[7];
        Wres  = (const float*)d_in[8];
        bias  = (const float*)d_in[9];
        gamma = (const float*)d_in[10];
        beta  = (const float*)d_in[11];
        eidx  = (const int*)  d_in[12];
    }
    const int* esrc = eidx;
    const int* edst = eidx + EN;
    float* out = (float*)d_out;

    cudaFuncSetAttribute(node_gemm_tc, cudaFuncAttributeMaxDynamicSharedMemorySize, NODE_SMEM);
    cudaFuncSetAttribute(edge_kernel_tc, cudaFuncAttributeMaxDynamicSharedMemorySize, EDGE_SMEM);

    zero_kernel<<<(NN * HH + 255) / 256, 256>>>();
    node_gemm_tc<<<dim3((NN + 127) / 128, 6), 256, NODE_SMEM>>>(x, Wl, bl, Wr, br, Wres, bias);
    edge_kernel_tc<<<EN / 128, 256, EDGE_SMEM>>>(ea, We, att, esrc, edst);
    scan_kernel<<<1, 1024>>>();
    fill_kernel<<<(EN + 255) / 256, 256>>>(edst);
    aggregate_ln_kernel<<<NN, 256>>>(esrc, gamma, beta, out);
}

// round 11
// speedup vs baseline: 3.3412x; 1.1818x over previous
#include <cuda_runtime.h>
#include <cuda_bf16.h>
#include <cstdint>

#define NN   50000
#define EN   800000
#define DD   256
#define HH   8
#define DE   64
#define NEG  0.2f

// ---------------- device scratch ----------------
__device__ float    g_xl[(size_t)NN * DD];
__device__ float    g_xr[(size_t)NN * DD];
__device__ float    g_base[(size_t)NN * DD];
__device__ uint32_t g_xlh[(size_t)NN * (DD / 2)];   // bf16x2 mirror of xl
__device__ uint32_t g_xrh[(size_t)NN * (DD / 2)];   // bf16x2 mirror of xr
__device__ float    g_w[(size_t)EN * HH];
__device__ float    g_denom[(size_t)NN * HH];
__device__ int      g_counts[NN];
__device__ int      g_offsets[NN + 1];
__device__ int      g_cursor[NN];
__device__ int      g_csr[EN];
__device__ int      g_bsum[256];

// ---------------- helpers ----------------
__device__ __forceinline__ uint32_t s2u(const void* p) {
    uint32_t a;
    asm("{ .reg .u64 t; cvta.to.shared.u64 t, %1; cvt.u32.u64 %0, t; }" : "=r"(a) : "l"(p));
    return a;
}
__device__ __forceinline__ void ldsm_x4(uint32_t* r, uint32_t addr) {
    asm volatile("ldmatrix.sync.aligned.m8n8.x4.shared.b16 {%0,%1,%2,%3}, [%4];"
        : "=r"(r[0]), "=r"(r[1]), "=r"(r[2]), "=r"(r[3]) : "r"(addr));
}
__device__ __forceinline__ void mma16816(float* c, const uint32_t* a, uint32_t b0, uint32_t b1) {
    asm volatile("mma.sync.aligned.m16n8k16.row.col.f32.bf16.bf16.f32 "
        "{%0,%1,%2,%3}, {%4,%5,%6,%7}, {%8,%9}, {%0,%1,%2,%3};"
        : "+f"(c[0]), "+f"(c[1]), "+f"(c[2]), "+f"(c[3])
        : "r"(a[0]), "r"(a[1]), "r"(a[2]), "r"(a[3]), "r"(b0), "r"(b1));
}
__device__ __forceinline__ uint2 pack4(float4 v, bool lo) {
    __nv_bfloat16 h0 = __float2bfloat16(v.x), h1 = __float2bfloat16(v.y);
    __nv_bfloat16 h2 = __float2bfloat16(v.z), h3 = __float2bfloat16(v.w);
    if (lo) {
        h0 = __float2bfloat16(v.x - __bfloat162float(h0));
        h1 = __float2bfloat16(v.y - __bfloat162float(h1));
        h2 = __float2bfloat16(v.z - __bfloat162float(h2));
        h3 = __float2bfloat16(v.w - __bfloat162float(h3));
    }
    uint2 r;
    r.x = ((uint32_t)__bfloat16_as_ushort(h1) << 16) | __bfloat16_as_ushort(h0);
    r.y = ((uint32_t)__bfloat16_as_ushort(h3) << 16) | __bfloat16_as_ushort(h2);
    return r;
}
__device__ __forceinline__ uint32_t bfpack2(float a, float b) {
    __nv_bfloat162 h;
    h.x = __float2bfloat16(a);
    h.y = __float2bfloat16(b);
    return *(uint32_t*)&h;
}
__device__ __forceinline__ float2 unpk(uint32_t u) {
    __nv_bfloat162 h = *(__nv_bfloat162*)&u;
    return __bfloat1622float2(h);
}

// fragment address helpers (pitch 40 bf16 per row; base = byte addr of tile)
__device__ __forceinline__ uint32_t a_frag_addr(uint32_t base, int mrow0, int kk, int lane) {
    int row = mrow0 + (lane & 15);
    int col = kk + ((lane >> 4) << 3);
    return base + (uint32_t)(row * 40 + col) * 2;
}
__device__ __forceinline__ uint32_t b_frag_addr(uint32_t base, int n0, int kk, int lane) {
    int row = n0 + (lane & 7) + ((lane >> 4) << 3);
    int col = kk + (((lane >> 3) & 1) << 3);
    return base + (uint32_t)(row * 40 + col) * 2;
}

// single-pass K=32 chunk
__device__ __forceinline__ void mma_chunk1(
    float acc[2][8][4], uint32_t ab, uint32_t bb, int mwarp, int nwarp, int lane)
{
#pragma unroll
    for (int ks = 0; ks < 32; ks += 16) {
        uint32_t af[2][4];
        ldsm_x4(af[0], a_frag_addr(ab, mwarp * 32, ks, lane));
        ldsm_x4(af[1], a_frag_addr(ab, mwarp * 32 + 16, ks, lane));
#pragma unroll
        for (int ng = 0; ng < 4; ng++) {
            uint32_t bf[4];
            ldsm_x4(bf, b_frag_addr(bb, nwarp * 64 + ng * 16, ks, lane));
            mma16816(acc[0][2 * ng + 0], af[0], bf[0], bf[1]);
            mma16816(acc[0][2 * ng + 1], af[0], bf[2], bf[3]);
            mma16816(acc[1][2 * ng + 0], af[1], bf[0], bf[1]);
            mma16816(acc[1][2 * ng + 1], af[1], bf[2], bf[3]);
        }
    }
}
// 3-pass split chunk (node GEMM precision path)
__device__ __forceinline__ void mma_chunk3(
    float acc[2][8][4],
    uint32_t aHi, uint32_t aLo, uint32_t bHi, uint32_t bLo,
    int mwarp, int nwarp, int lane)
{
    mma_chunk1(acc, aHi, bHi, mwarp, nwarp, lane);
    mma_chunk1(acc, aLo, bHi, mwarp, nwarp, lane);
    mma_chunk1(acc, aHi, bLo, mwarp, nwarp, lane);
}

// ---------------- K0: zero ----------------
__global__ void zero_kernel() {
    int i = blockIdx.x * blockDim.x + threadIdx.x;
    if (i < NN * HH) g_denom[i] = 0.f;
    if (i < NN) g_counts[i] = 0;
    if (i == 0) g_offsets[NN] = EN;
}

// ---------------- node GEMM (HMMA, 3-pass split): out = x @ W^T + b ----------------
#define NA_HI 0u
#define NA_LO 10240u
#define NB_HI 20480u
#define NB_LO 30720u
#define NODE_SMEM 40960

__global__ __launch_bounds__(256, 1) void node_gemm_tc(
    const float* __restrict__ x,
    const float* __restrict__ Wl, const float* __restrict__ bl,
    const float* __restrict__ Wr, const float* __restrict__ br,
    const float* __restrict__ Wres, const float* __restrict__ bres)
{
    extern __shared__ char smem[];
    uint32_t sb = s2u(smem);
    int tid = threadIdx.x, lane = tid & 31, wid = tid >> 5;
    int mwarp = wid >> 1, nwarp = wid & 1;
    int m0 = blockIdx.x * 128;
    int mat = blockIdx.y >> 1;
    int nhalf = blockIdx.y & 1;

    const float* W  = (mat == 0) ? Wl : ((mat == 1) ? Wr : Wres);
    const float* bv = (mat == 0) ? bl : ((mat == 1) ? br : bres);
    float* out      = (mat == 0) ? g_xl : ((mat == 1) ? g_xr : g_base);
    uint32_t* outh  = (mat == 0) ? g_xlh : ((mat == 1) ? g_xrh : (uint32_t*)0);
    int ncol0 = nhalf * 128;

    float acc[2][8][4];
#pragma unroll
    for (int i = 0; i < 2; i++)
#pragma unroll
        for (int j = 0; j < 8; j++)
#pragma unroll
            for (int k = 0; k < 4; k++) acc[i][j][k] = 0.f;

    for (int c = 0; c < 8; c++) {
        int k0 = c * 32;
        __syncthreads();
#pragma unroll
        for (int it = 0; it < 4; it++) {
            int i = tid + it * 256;
            int r = i >> 3, kq = (i & 7) << 2;
            int m = m0 + r; if (m >= NN) m = NN - 1;
            float4 v = __ldg((const float4*)(x + (size_t)m * DD + k0 + kq));
            uint32_t off = (uint32_t)(r * 40 + kq) * 2;
            *(uint2*)(smem + NA_HI + off) = pack4(v, false);
            *(uint2*)(smem + NA_LO + off) = pack4(v, true);
        }
#pragma unroll
        for (int it = 0; it < 4; it++) {
            int i = tid + it * 256;
            int r = i >> 3, kq = (i & 7) << 2;
            float4 v = __ldg((const float4*)(W + (size_t)(ncol0 + r) * DD + k0 + kq));
            uint32_t off = (uint32_t)(r * 40 + kq) * 2;
            *(uint2*)(smem + NB_HI + off) = pack4(v, false);
            *(uint2*)(smem + NB_LO + off) = pack4(v, true);
        }
        __syncthreads();
        mma_chunk3(acc, sb + NA_HI, sb + NA_LO, sb + NB_HI, sb + NB_LO, mwarp, nwarp, lane);
    }

#pragma unroll
    for (int mt = 0; mt < 2; mt++) {
        int row = m0 + mwarp * 32 + mt * 16 + (lane >> 2);
#pragma unroll
        for (int nt = 0; nt < 8; nt++) {
            int col = ncol0 + nwarp * 64 + nt * 8 + ((lane & 3) << 1);
            float b0 = __ldg(&bv[col]), b1 = __ldg(&bv[col + 1]);
            if (row < NN) {
                float2 v = {acc[mt][nt][0] + b0, acc[mt][nt][1] + b1};
                *(float2*)(out + (size_t)row * DD + col) = v;
                if (outh) outh[(size_t)row * 128 + (col >> 1)] = bfpack2(v.x, v.y);
            }
            if (row + 8 < NN) {
                float2 v = {acc[mt][nt][2] + b0, acc[mt][nt][3] + b1};
                *(float2*)(out + (size_t)(row + 8) * DD + col) = v;
                if (outh) outh[(size_t)(row + 8) * 128 + (col >> 1)] = bfpack2(v.x, v.y);
            }
        }
    }
}

// ---------------- edge kernel: fused ee GEMM (single-pass bf16) + logits + hist ----------------
#define EE_OFF  0u                  // 128 x 133 u32 = 68096 B
#define EA_OFF  68096u              // 2 chunks x 128 x 40 bf16 = 20480 B
#define EB_OFF  (EA_OFF + 20480u)   // 2 chunks x 128 x 40 bf16 = 20480 B
#define EIDX    (EB_OFF + 20480u)
#define EDGE_SMEM (EIDX + 1024u)    // 110080 -> 2 CTAs/SM

__global__ __launch_bounds__(256, 2) void edge_kernel_tc(
    const float* __restrict__ ea,
    const float* __restrict__ We,
    const float* __restrict__ att,
    const int* __restrict__ esrc,
    const int* __restrict__ edst)
{
    extern __shared__ char smem[];
    uint32_t sb = s2u(smem);
    int tid = threadIdx.x, lane = tid & 31, wid = tid >> 5;
    int mwarp = wid >> 1, nwarp = wid & 1;
    int e0 = blockIdx.x * 128;
    int* sSrc = (int*)(smem + EIDX);
    int* sDst = sSrc + 128;
    uint32_t* ee32 = (uint32_t*)(smem + EE_OFF);

    if (tid < 128) {
        int s = esrc[e0 + tid];
        int d = edst[e0 + tid];
        sSrc[tid] = s;
        sDst[tid] = d;
        atomicAdd(&g_counts[d], 1);   // fused histogram
    }

    // stage A (edge_attr 128x64) single-pass hi bf16
#pragma unroll
    for (int it = 0; it < 8; it++) {
        int i = tid + it * 256;
        int r = i >> 4, kq = (i & 15) << 2;
        float4 v = __ldg((const float4*)(ea + (size_t)(e0 + r) * DE + kq));
        int ch = kq >> 5, kc = kq & 31;
        uint32_t off = (uint32_t)(ch * 5120 + r * 40 + kc) * 2;
        *(uint2*)(smem + EA_OFF + off) = pack4(v, false);
    }

    for (int nh = 0; nh < 2; nh++) {
        if (nh) __syncthreads();
#pragma unroll
        for (int it = 0; it < 8; it++) {
            int i = tid + it * 256;
            int r = i >> 4, kq = (i & 15) << 2;
            float4 v = __ldg((const float4*)(We + (size_t)(nh * 128 + r) * DE + kq));
            int ch = kq >> 5, kc = kq & 31;
            uint32_t off = (uint32_t)(ch * 5120 + r * 40 + kc) * 2;
            *(uint2*)(smem + EB_OFF + off) = pack4(v, false);
        }
        __syncthreads();

        float acc[2][8][4];
#pragma unroll
        for (int i = 0; i < 2; i++)
#pragma unroll
            for (int j = 0; j < 8; j++)
#pragma unroll
                for (int k = 0; k < 4; k++) acc[i][j][k] = 0.f;

#pragma unroll
        for (int c = 0; c < 2; c++)
            mma_chunk1(acc, sb + EA_OFF + c * 10240, sb + EB_OFF + c * 10240,
                       mwarp, nwarp, lane);

#pragma unroll
        for (int mt = 0; mt < 2; mt++) {
            int el = mwarp * 32 + mt * 16 + (lane >> 2);
#pragma unroll
            for (int nt = 0; nt < 8; nt++) {
                int w = nh * 64 + nwarp * 32 + nt * 4 + (lane & 3);
                ee32[el * 133 + w]       = bfpack2(acc[mt][nt][0], acc[mt][nt][1]);
                ee32[(el + 8) * 133 + w] = bfpack2(acc[mt][nt][2], acc[mt][nt][3]);
            }
        }
    }
    __syncthreads();

    // logit phase: quad of lanes per edge; xl/xr read as bf16x2 (halved traffic)
    int q = tid & 3;
    for (int rep = 0; rep < 2; rep++) {
        int el = (tid >> 2) + rep * 64;
        int s = sSrc[el];
        int d = sDst[el];
        const uint32_t* xlp = g_xlh + (size_t)s * 128;
        const uint32_t* xrp = g_xrh + (size_t)d * 128;
        uint32_t eeb = el * 133 + q * 4;
#pragma unroll
        for (int h = 0; h < 8; h++) {
            int cb  = h * 32 + q * 8;   // float channel base
            int cb2 = h * 16 + q * 4;   // bf16x2 index base
            uint4 U = __ldg((const uint4*)(xlp + cb2));
            uint4 R = __ldg((const uint4*)(xrp + cb2));
            float2 u0 = unpk(U.x), u1 = unpk(U.y), u2 = unpk(U.z), u3 = unpk(U.w);
            float2 r0 = unpk(R.x), r1 = unpk(R.y), r2 = unpk(R.z), r3 = unpk(R.w);
            float2 f0 = unpk(ee32[eeb + h * 16 + 0]);
            float2 f1 = unpk(ee32[eeb + h * 16 + 1]);
            float2 f2 = unpk(ee32[eeb + h * 16 + 2]);
            float2 f3 = unpk(ee32[eeb + h * 16 + 3]);
            float4 a0 = __ldg((const float4*)(att + cb));
            float4 a1 = __ldg((const float4*)(att + cb + 4));
            float p = 0.f, z;
            z = u0.x + r0.x + f0.x; z = (z > 0.f) ? z : NEG * z; p += z * a0.x;
            z = u0.y + r0.y + f0.y; z = (z > 0.f) ? z : NEG * z; p += z * a0.y;
            z = u1.x + r1.x + f1.x; z = (z > 0.f) ? z : NEG * z; p += z * a0.z;
            z = u1.y + r1.y + f1.y; z = (z > 0.f) ? z : NEG * z; p += z * a0.w;
            z = u2.x + r2.x + f2.x; z = (z > 0.f) ? z : NEG * z; p += z * a1.x;
            z = u2.y + r2.y + f2.y; z = (z > 0.f) ? z : NEG * z; p += z * a1.y;
            z = u3.x + r3.x + f3.x; z = (z > 0.f) ? z : NEG * z; p += z * a1.z;
            z = u3.y + r3.y + f3.y; z = (z > 0.f) ? z : NEG * z; p += z * a1.w;
            p += __shfl_xor_sync(0xffffffffu, p, 1);
            p += __shfl_xor_sync(0xffffffffu, p, 2);
            if (q == 0) {
                float w = __expf(p);
                g_w[(size_t)(e0 + el) * HH + h] = w;
                atomicAdd(&g_denom[(size_t)d * HH + h], w);
            }
        }
    }
}

// ---------------- scan: 3-kernel device-wide exclusive scan of g_counts ----------------
#define SCAN_BLOCKS ((NN + 255) / 256)   // 196

__global__ __launch_bounds__(256) void scan_part() {
    int i = blockIdx.x * 256 + threadIdx.x;
    int c = (i < NN) ? g_counts[i] : 0;
    int v = c;
#pragma unroll
    for (int off = 16; off; off >>= 1) v += __shfl_down_sync(0xffffffffu, v, off);
    __shared__ int ws[8];
    if ((threadIdx.x & 31) == 0) ws[threadIdx.x >> 5] = v;
    __syncthreads();
    if (threadIdx.x == 0) {
        int s = 0;
#pragma unroll
        for (int j = 0; j < 8; j++) s += ws[j];
        g_bsum[blockIdx.x] = s;
    }
}

__global__ __launch_bounds__(256) void scan_mid() {
    __shared__ int ss[256];
    int tid = threadIdx.x;
    int v = (tid < SCAN_BLOCKS) ? g_bsum[tid] : 0;
    ss[tid] = v;
    __syncthreads();
#pragma unroll
    for (int off = 1; off < 256; off <<= 1) {
        int t = (tid >= off) ? ss[tid - off] : 0;
        __syncthreads();
        ss[tid] += t;
        __syncthreads();
    }
    if (tid < SCAN_BLOCKS) g_bsum[tid] = ss[tid] - v;   // exclusive
}

__global__ __launch_bounds__(256) void scan_final() {
    __shared__ int ss[256];
    int tid = threadIdx.x;
    int i = blockIdx.x * 256 + tid;
    int c = (i < NN) ? g_counts[i] : 0;
    ss[tid] = c;
    __syncthreads();
#pragma unroll
    for (int off = 1; off < 256; off <<= 1) {
        int t = (tid >= off) ? ss[tid - off] : 0;
        __syncthreads();
        ss[tid] += t;
        __syncthreads();
    }
    if (i < NN) {
        int excl = ss[tid] - c + g_bsum[blockIdx.x];
        g_offsets[i] = excl;
        g_cursor[i] = excl;
    }
}

__global__ void fill_kernel(const int* __restrict__ edst) {
    int e = blockIdx.x * blockDim.x + threadIdx.x;
    if (e < EN) {
        int d = edst[e];
        int p = atomicAdd(&g_cursor[d], 1);
        g_csr[p] = e;
    }
}

// ---------------- aggregation + residual + LayerNorm (stage-then-stream) ----------------
__global__ __launch_bounds__(256) void aggregate_ln_kernel(
    const int* __restrict__ esrc,
    const float* __restrict__ gamma,
    const float* __restrict__ beta,
    float* __restrict__ out)
{
    int i = blockIdx.x;
    int tid = threadIdx.x;
    int h = tid >> 5;
    __shared__ int   ssrc[64];
    __shared__ float sw[64 * 8];
    __shared__ float sred[8], sred2[8];

    int p0 = g_offsets[i], p1 = g_offsets[i + 1];
    float acc = 0.f;

    for (int base = p0; base < p1; base += 64) {
        int n = min(64, p1 - base);
        __syncthreads();
        if (tid < n) {
            int e = __ldg(&g_csr[base + tid]);
            ssrc[tid] = __ldg(&esrc[e]);
            const float* wp = g_w + (size_t)e * HH;
            float4 w0 = __ldg((const float4*)wp);
            float4 w1 = __ldg((const float4*)(wp + 4));
            *(float4*)&sw[tid * 8]     = w0;
            *(float4*)&sw[tid * 8 + 4] = w1;
        }
        __syncthreads();
        int j = 0;
        for (; j + 4 <= n; j += 4) {
            int s0 = ssrc[j], s1 = ssrc[j + 1], s2 = ssrc[j + 2], s3 = ssrc[j + 3];
            float w0 = sw[j * 8 + h], w1 = sw[(j + 1) * 8 + h];
            float w2 = sw[(j + 2) * 8 + h], w3 = sw[(j + 3) * 8 + h];
            float x0 = __ldg(&g_xl[(size_t)s0 * DD + tid]);
            float x1 = __ldg(&g_xl[(size_t)s1 * DD + tid]);
            float x2 = __ldg(&g_xl[(size_t)s2 * DD + tid]);
            float x3 = __ldg(&g_xl[(size_t)s3 * DD + tid]);
            acc += x0 * w0;
            acc += x1 * w1;
            acc += x2 * w2;
            acc += x3 * w3;
        }
        for (; j < n; j++)
            acc += __ldg(&g_xl[(size_t)ssrc[j] * DD + tid]) * sw[j * 8 + h];
    }

    float den = __ldg(&g_denom[(size_t)i * HH + h]);
    float invd = (den > 0.f) ? (1.f / den) : 0.f;
    float v = acc * invd + g_base[(size_t)i * DD + tid];

    float s1 = v, s2 = v * v;
#pragma unroll
    for (int off = 16; off; off >>= 1) {
        s1 += __shfl_down_sync(0xffffffffu, s1, off);
        s2 += __shfl_down_sync(0xffffffffu, s2, off);
    }
    if ((tid & 31) == 0) { sred[tid >> 5] = s1; sred2[tid >> 5] = s2; }
    __syncthreads();
    if (tid == 0) {
        float a = 0.f, b = 0.f;
#pragma unroll
        for (int j = 0; j < 8; j++) { a += sred[j]; b += sred2[j]; }
        float mu = a * (1.f / DD);
        float var = b * (1.f / DD) - mu * mu;
        sred[0] = mu;
        sred2[0] = rsqrtf(fmaxf(var, 0.f) + 1e-5f);
    }
    __syncthreads();
    float mu = sred[0], rstd = sred2[0];
    out[(size_t)i * DD + tid] = (v - mu) * rstd * __ldg(&gamma[tid]) + __ldg(&beta[tid]);
}

// ---------------- launch ----------------
extern "C" void kernel_launch(void* const* d_in, const int* in_sizes, int n_in,
                              void* d_out, int out_size)
{
    const float *x, *ea, *Wl, *bl, *Wr, *br, *We, *att, *Wres, *bias, *gamma, *beta;
    const int* eidx;

    if (n_in >= 13 && in_sizes[2] == 2 * EN) {
        x     = (const float*)d_in[0];
        ea    = (const float*)d_in[1];
        eidx  = (const int*)  d_in[2];
        Wl    = (const float*)d_in[3];
        bl    = (const float*)d_in[4];
        Wr    = (const float*)d_in[5];
        br    = (const float*)d_in[6];
        We    = (const float*)d_in[7];
        att   = (const float*)d_in[8];
        Wres  = (const float*)d_in[9];
        bias  = (const float*)d_in[10];
        gamma = (const float*)d_in[11];
        beta  = (const float*)d_in[12];
    } else {
        x     = (const float*)d_in[0];
        ea    = (const float*)d_in[1];
        Wl    = (const float*)d_in[2];
        bl    = (const float*)d_in[3];
        Wr    = (const float*)d_in[4];
        br    = (const float*)d_in[5];
        We    = (const float*)d_in[6];
        att   = (const float*)d_in[7];
        Wres  = (const float*)d_in[8];
        bias  = (const float*)d_in[9];
        gamma = (const float*)d_in[10];
        beta  = (const float*)d_in[11];
        eidx  = (const int*)  d_in[12];
    }
    const int* esrc = eidx;
    const int* edst = eidx + EN;
    float* out = (float*)d_out;

    cudaFuncSetAttribute(node_gemm_tc, cudaFuncAttributeMaxDynamicSharedMemorySize, NODE_SMEM);
    cudaFuncSetAttribute(edge_kernel_tc, cudaFuncAttributeMaxDynamicSharedMemorySize, EDGE_SMEM);

    zero_kernel<<<(NN * HH + 255) / 256, 256>>>();
    node_gemm_tc<<<dim3((NN + 127) / 128, 6), 256, NODE_SMEM>>>(x, Wl, bl, Wr, br, Wres, bias);
    edge_kernel_tc<<<EN / 128, 256, EDGE_SMEM>>>(ea, We, att, esrc, edst);
    scan_part<<<SCAN_BLOCKS, 256>>>();
    scan_mid<<<1, 256>>>();
    scan_final<<<SCAN_BLOCKS, 256>>>();
    fill_kernel<<<(EN + 255) / 256, 256>>>(edst);
    aggregate_ln_kernel<<<NN, 256>>>(esrc, gamma, beta, out);
}

// round 13
// speedup vs baseline: 4.0376x; 1.2084x over previous
#include <cuda_runtime.h>
#include <cuda_bf16.h>
#include <cstdint>

#define NN   50000
#define EN   800000
#define DD   256
#define HH   8
#define DE   64
#define NEG  0.2f

// ---------------- device scratch ----------------
__device__ float    g_xl[(size_t)NN * DD];
__device__ float    g_xr[(size_t)NN * DD];
__device__ float    g_base[(size_t)NN * DD];
__device__ uint32_t g_xlh[(size_t)NN * (DD / 2)];   // bf16x2 mirror of xl
__device__ uint32_t g_xrh[(size_t)NN * (DD / 2)];   // bf16x2 mirror of xr
__device__ float    g_w[(size_t)EN * HH];
__device__ float    g_denom[(size_t)NN * HH];
__device__ int      g_counts[NN];
__device__ int      g_offsets[NN + 1];
__device__ int      g_cursor[NN];
__device__ int      g_csr[EN];
__device__ int      g_bsum[256];

// ---------------- helpers ----------------
__device__ __forceinline__ uint32_t s2u(const void* p) {
    uint32_t a;
    asm("{ .reg .u64 t; cvta.to.shared.u64 t, %1; cvt.u32.u64 %0, t; }" : "=r"(a) : "l"(p));
    return a;
}
__device__ __forceinline__ void ldsm_x4(uint32_t* r, uint32_t addr) {
    asm volatile("ldmatrix.sync.aligned.m8n8.x4.shared.b16 {%0,%1,%2,%3}, [%4];"
        : "=r"(r[0]), "=r"(r[1]), "=r"(r[2]), "=r"(r[3]) : "r"(addr));
}
__device__ __forceinline__ void mma16816(float* c, const uint32_t* a, uint32_t b0, uint32_t b1) {
    asm volatile("mma.sync.aligned.m16n8k16.row.col.f32.bf16.bf16.f32 "
        "{%0,%1,%2,%3}, {%4,%5,%6,%7}, {%8,%9}, {%0,%1,%2,%3};"
        : "+f"(c[0]), "+f"(c[1]), "+f"(c[2]), "+f"(c[3])
        : "r"(a[0]), "r"(a[1]), "r"(a[2]), "r"(a[3]), "r"(b0), "r"(b1));
}
__device__ __forceinline__ uint2 pack4(float4 v, bool lo) {
    __nv_bfloat16 h0 = __float2bfloat16(v.x), h1 = __float2bfloat16(v.y);
    __nv_bfloat16 h2 = __float2bfloat16(v.z), h3 = __float2bfloat16(v.w);
    if (lo) {
        h0 = __float2bfloat16(v.x - __bfloat162float(h0));
        h1 = __float2bfloat16(v.y - __bfloat162float(h1));
        h2 = __float2bfloat16(v.z - __bfloat162float(h2));
        h3 = __float2bfloat16(v.w - __bfloat162float(h3));
    }
    uint2 r;
    r.x = ((uint32_t)__bfloat16_as_ushort(h1) << 16) | __bfloat16_as_ushort(h0);
    r.y = ((uint32_t)__bfloat16_as_ushort(h3) << 16) | __bfloat16_as_ushort(h2);
    return r;
}
__device__ __forceinline__ uint32_t bfpack2(float a, float b) {
    __nv_bfloat162 h;
    h.x = __float2bfloat16(a);
    h.y = __float2bfloat16(b);
    return *(uint32_t*)&h;
}
__device__ __forceinline__ float2 unpk(uint32_t u) {
    __nv_bfloat162 h = *(__nv_bfloat162*)&u;
    return __bfloat1622float2(h);
}

// fragment address helpers (pitch 40 bf16 per row; base = byte addr of tile)
__device__ __forceinline__ uint32_t a_frag_addr(uint32_t base, int mrow0, int kk, int lane) {
    int row = mrow0 + (lane & 15);
    int col = kk + ((lane >> 4) << 3);
    return base + (uint32_t)(row * 40 + col) * 2;
}
__device__ __forceinline__ uint32_t b_frag_addr(uint32_t base, int n0, int kk, int lane) {
    int row = n0 + (lane & 7) + ((lane >> 4) << 3);
    int col = kk + (((lane >> 3) & 1) << 3);
    return base + (uint32_t)(row * 40 + col) * 2;
}

// single-pass K=32 chunk
__device__ __forceinline__ void mma_chunk1(
    float acc[2][8][4], uint32_t ab, uint32_t bb, int mwarp, int nwarp, int lane)
{
#pragma unroll
    for (int ks = 0; ks < 32; ks += 16) {
        uint32_t af[2][4];
        ldsm_x4(af[0], a_frag_addr(ab, mwarp * 32, ks, lane));
        ldsm_x4(af[1], a_frag_addr(ab, mwarp * 32 + 16, ks, lane));
#pragma unroll
        for (int ng = 0; ng < 4; ng++) {
            uint32_t bf[4];
            ldsm_x4(bf, b_frag_addr(bb, nwarp * 64 + ng * 16, ks, lane));
            mma16816(acc[0][2 * ng + 0], af[0], bf[0], bf[1]);
            mma16816(acc[0][2 * ng + 1], af[0], bf[2], bf[3]);
            mma16816(acc[1][2 * ng + 0], af[1], bf[0], bf[1]);
            mma16816(acc[1][2 * ng + 1], af[1], bf[2], bf[3]);
        }
    }
}
// 3-pass split chunk (node GEMM precision path)
__device__ __forceinline__ void mma_chunk3(
    float acc[2][8][4],
    uint32_t aHi, uint32_t aLo, uint32_t bHi, uint32_t bLo,
    int mwarp, int nwarp, int lane)
{
    mma_chunk1(acc, aHi, bHi, mwarp, nwarp, lane);
    mma_chunk1(acc, aLo, bHi, mwarp, nwarp, lane);
    mma_chunk1(acc, aHi, bLo, mwarp, nwarp, lane);
}

// ---------------- K0: zero ----------------
__global__ void zero_kernel() {
    int i = blockIdx.x * blockDim.x + threadIdx.x;
    if (i < NN * HH) g_denom[i] = 0.f;
    if (i < NN) g_counts[i] = 0;
    if (i == 0) g_offsets[NN] = EN;
}

// ---------------- node GEMM (HMMA, 3-pass split, reg-prefetch pipeline) ----------------
#define NA_HI 0u
#define NA_LO 10240u
#define NB_HI 20480u
#define NB_LO 30720u
#define NODE_SMEM 40960

__global__ __launch_bounds__(256, 1) void node_gemm_tc(
    const float* __restrict__ x,
    const float* __restrict__ Wl, const float* __restrict__ bl,
    const float* __restrict__ Wr, const float* __restrict__ br,
    const float* __restrict__ Wres, const float* __restrict__ bres)
{
    extern __shared__ char smem[];
    uint32_t sb = s2u(smem);
    int tid = threadIdx.x, lane = tid & 31, wid = tid >> 5;
    int mwarp = wid >> 1, nwarp = wid & 1;
    int m0 = blockIdx.x * 128;
    int mat = blockIdx.y >> 1;
    int nhalf = blockIdx.y & 1;

    const float* W  = (mat == 0) ? Wl : ((mat == 1) ? Wr : Wres);
    const float* bv = (mat == 0) ? bl : ((mat == 1) ? br : bres);
    float* out      = (mat == 0) ? g_xl : ((mat == 1) ? g_xr : g_base);
    uint32_t* outh  = (mat == 0) ? g_xlh : ((mat == 1) ? g_xrh : (uint32_t*)0);
    int ncol0 = nhalf * 128;

    // per-thread fixed staging coordinates (4 float4s per tile)
    int srow[4], skq[4];
    const float* aptr[4];
    const float* bptr[4];
#pragma unroll
    for (int it = 0; it < 4; it++) {
        int i = tid + it * 256;
        int r = i >> 3, kq = (i & 7) << 2;
        srow[it] = r; skq[it] = kq;
        int m = m0 + r; if (m >= NN) m = NN - 1;
        aptr[it] = x + (size_t)m * DD + kq;
        bptr[it] = W + (size_t)(ncol0 + r) * DD + kq;
    }

    float acc[2][8][4];
#pragma unroll
    for (int i = 0; i < 2; i++)
#pragma unroll
        for (int j = 0; j < 8; j++)
#pragma unroll
            for (int k = 0; k < 4; k++) acc[i][j][k] = 0.f;

    float4 ra[4], rb[4];
#pragma unroll
    for (int it = 0; it < 4; it++) {
        ra[it] = __ldg((const float4*)(aptr[it]));
        rb[it] = __ldg((const float4*)(bptr[it]));
    }

    for (int c = 0; c < 8; c++) {
        __syncthreads();   // previous mma done reading smem
#pragma unroll
        for (int it = 0; it < 4; it++) {
            uint32_t off = (uint32_t)(srow[it] * 40 + skq[it]) * 2;
            *(uint2*)(smem + NA_HI + off) = pack4(ra[it], false);
            *(uint2*)(smem + NA_LO + off) = pack4(ra[it], true);
            *(uint2*)(smem + NB_HI + off) = pack4(rb[it], false);
            *(uint2*)(smem + NB_LO + off) = pack4(rb[it], true);
        }
        __syncthreads();
        if (c < 7) {
            int k0 = (c + 1) * 32;
#pragma unroll
            for (int it = 0; it < 4; it++) {
                ra[it] = __ldg((const float4*)(aptr[it] + k0));
                rb[it] = __ldg((const float4*)(bptr[it] + k0));
            }
        }
        mma_chunk3(acc, sb + NA_HI, sb + NA_LO, sb + NB_HI, sb + NB_LO, mwarp, nwarp, lane);
    }

#pragma unroll
    for (int mt = 0; mt < 2; mt++) {
        int row = m0 + mwarp * 32 + mt * 16 + (lane >> 2);
#pragma unroll
        for (int nt = 0; nt < 8; nt++) {
            int col = ncol0 + nwarp * 64 + nt * 8 + ((lane & 3) << 1);
            float b0 = __ldg(&bv[col]), b1 = __ldg(&bv[col + 1]);
            if (row < NN) {
                float2 v = {acc[mt][nt][0] + b0, acc[mt][nt][1] + b1};
                *(float2*)(out + (size_t)row * DD + col) = v;
                if (outh) outh[(size_t)row * 128 + (col >> 1)] = bfpack2(v.x, v.y);
            }
            if (row + 8 < NN) {
                float2 v = {acc[mt][nt][2] + b0, acc[mt][nt][3] + b1};
                *(float2*)(out + (size_t)(row + 8) * DD + col) = v;
                if (outh) outh[(size_t)(row + 8) * 128 + (col >> 1)] = bfpack2(v.x, v.y);
            }
        }
    }
}

// ---------------- edge kernel: fused ee GEMM (single-pass bf16) + logits + hist ----------------
#define EE_OFF  0u                  // 128 x 133 u32 = 68096 B
#define EA_OFF  68096u              // 2 chunks x 128 x 40 bf16 = 20480 B
#define EB_OFF  (EA_OFF + 20480u)   // 2 chunks x 128 x 40 bf16 = 20480 B
#define EIDX    (EB_OFF + 20480u)
#define EDGE_SMEM (EIDX + 1024u)    // 110080 -> 2 CTAs/SM

__global__ __launch_bounds__(256, 2) void edge_kernel_tc(
    const float* __restrict__ ea,
    const float* __restrict__ We,
    const float* __restrict__ att,
    const int* __restrict__ esrc,
    const int* __restrict__ edst)
{
    extern __shared__ char smem[];
    uint32_t sb = s2u(smem);
    int tid = threadIdx.x, lane = tid & 31, wid = tid >> 5;
    int mwarp = wid >> 1, nwarp = wid & 1;
    int e0 = blockIdx.x * 128;
    int* sSrc = (int*)(smem + EIDX);
    int* sDst = sSrc + 128;
    uint32_t* ee32 = (uint32_t*)(smem + EE_OFF);

    if (tid < 128) {
        int s = esrc[e0 + tid];
        int d = edst[e0 + tid];
        sSrc[tid] = s;
        sDst[tid] = d;
        atomicAdd(&g_counts[d], 1);   // fused histogram
    }

    // stage A (edge_attr 128x64) single-pass hi bf16
#pragma unroll
    for (int it = 0; it < 8; it++) {
        int i = tid + it * 256;
        int r = i >> 4, kq = (i & 15) << 2;
        float4 v = __ldg((const float4*)(ea + (size_t)(e0 + r) * DE + kq));
        int ch = kq >> 5, kc = kq & 31;
        uint32_t off = (uint32_t)(ch * 5120 + r * 40 + kc) * 2;
        *(uint2*)(smem + EA_OFF + off) = pack4(v, false);
    }

    for (int nh = 0; nh < 2; nh++) {
        if (nh) __syncthreads();
#pragma unroll
        for (int it = 0; it < 8; it++) {
            int i = tid + it * 256;
            int r = i >> 4, kq = (i & 15) << 2;
            float4 v = __ldg((const float4*)(We + (size_t)(nh * 128 + r) * DE + kq));
            int ch = kq >> 5, kc = kq & 31;
            uint32_t off = (uint32_t)(ch * 5120 + r * 40 + kc) * 2;
            *(uint2*)(smem + EB_OFF + off) = pack4(v, false);
        }
        __syncthreads();

        float acc[2][8][4];
#pragma unroll
        for (int i = 0; i < 2; i++)
#pragma unroll
            for (int j = 0; j < 8; j++)
#pragma unroll
                for (int k = 0; k < 4; k++) acc[i][j][k] = 0.f;

#pragma unroll
        for (int c = 0; c < 2; c++)
            mma_chunk1(acc, sb + EA_OFF + c * 10240, sb + EB_OFF + c * 10240,
                       mwarp, nwarp, lane);

#pragma unroll
        for (int mt = 0; mt < 2; mt++) {
            int el = mwarp * 32 + mt * 16 + (lane >> 2);
#pragma unroll
            for (int nt = 0; nt < 8; nt++) {
                int w = nh * 64 + nwarp * 32 + nt * 4 + (lane & 3);
                ee32[el * 133 + w]       = bfpack2(acc[mt][nt][0], acc[mt][nt][1]);
                ee32[(el + 8) * 133 + w] = bfpack2(acc[mt][nt][2], acc[mt][nt][3]);
            }
        }
    }
    __syncthreads();

    // logit phase: quad of lanes per edge; xl/xr read as bf16x2
    int q = tid & 3;
    for (int rep = 0; rep < 2; rep++) {
        int el = (tid >> 2) + rep * 64;
        int s = sSrc[el];
        int d = sDst[el];
        const uint32_t* xlp = g_xlh + (size_t)s * 128;
        const uint32_t* xrp = g_xrh + (size_t)d * 128;
        uint32_t eeb = el * 133 + q * 4;
#pragma unroll
        for (int h = 0; h < 8; h++) {
            int cb  = h * 32 + q * 8;
            int cb2 = h * 16 + q * 4;
            uint4 U = __ldg((const uint4*)(xlp + cb2));
            uint4 R = __ldg((const uint4*)(xrp + cb2));
            float2 u0 = unpk(U.x), u1 = unpk(U.y), u2 = unpk(U.z), u3 = unpk(U.w);
            float2 r0 = unpk(R.x), r1 = unpk(R.y), r2 = unpk(R.z), r3 = unpk(R.w);
            float2 f0 = unpk(ee32[eeb + h * 16 + 0]);
            float2 f1 = unpk(ee32[eeb + h * 16 + 1]);
            float2 f2 = unpk(ee32[eeb + h * 16 + 2]);
            float2 f3 = unpk(ee32[eeb + h * 16 + 3]);
            float4 a0 = __ldg((const float4*)(att + cb));
            float4 a1 = __ldg((const float4*)(att + cb + 4));
            float p = 0.f, z;
            z = u0.x + r0.x + f0.x; z = (z > 0.f) ? z : NEG * z; p += z * a0.x;
            z = u0.y + r0.y + f0.y; z = (z > 0.f) ? z : NEG * z; p += z * a0.y;
            z = u1.x + r1.x + f1.x; z = (z > 0.f) ? z : NEG * z; p += z * a0.z;
            z = u1.y + r1.y + f1.y; z = (z > 0.f) ? z : NEG * z; p += z * a0.w;
            z = u2.x + r2.x + f2.x; z = (z > 0.f) ? z : NEG * z; p += z * a1.x;
            z = u2.y + r2.y + f2.y; z = (z > 0.f) ? z : NEG * z; p += z * a1.y;
            z = u3.x + r3.x + f3.x; z = (z > 0.f) ? z : NEG * z; p += z * a1.z;
            z = u3.y + r3.y + f3.y; z = (z > 0.f) ? z : NEG * z; p += z * a1.w;
            p += __shfl_xor_sync(0xffffffffu, p, 1);
            p += __shfl_xor_sync(0xffffffffu, p, 2);
            if (q == 0) {
                float w = __expf(p);
                g_w[(size_t)(e0 + el) * HH + h] = w;
                atomicAdd(&g_denom[(size_t)d * HH + h], w);
            }
        }
    }
}

// ---------------- scan: 3-kernel device-wide exclusive scan of g_counts ----------------
#define SCAN_BLOCKS ((NN + 255) / 256)   // 196

__global__ __launch_bounds__(256) void scan_part() {
    int i = blockIdx.x * 256 + threadIdx.x;
    int c = (i < NN) ? g_counts[i] : 0;
    int v = c;
#pragma unroll
    for (int off = 16; off; off >>= 1) v += __shfl_down_sync(0xffffffffu, v, off);
    __shared__ int ws[8];
    if ((threadIdx.x & 31) == 0) ws[threadIdx.x >> 5] = v;
    __syncthreads();
    if (threadIdx.x == 0) {
        int s = 0;
#pragma unroll
        for (int j = 0; j < 8; j++) s += ws[j];
        g_bsum[blockIdx.x] = s;
    }
}

__global__ __launch_bounds__(256) void scan_mid() {
    __shared__ int ss[256];
    int tid = threadIdx.x;
    int v = (tid < SCAN_BLOCKS) ? g_bsum[tid] : 0;
    ss[tid] = v;
    __syncthreads();
#pragma unroll
    for (int off = 1; off < 256; off <<= 1) {
        int t = (tid >= off) ? ss[tid - off] : 0;
        __syncthreads();
        ss[tid] += t;
        __syncthreads();
    }
    if (tid < SCAN_BLOCKS) g_bsum[tid] = ss[tid] - v;   // exclusive
}

__global__ __launch_bounds__(256) void scan_final() {
    __shared__ int ss[256];
    int tid = threadIdx.x;
    int i = blockIdx.x * 256 + tid;
    int c = (i < NN) ? g_counts[i] : 0;
    ss[tid] = c;
    __syncthreads();
#pragma unroll
    for (int off = 1; off < 256; off <<= 1) {
        int t = (tid >= off) ? ss[tid - off] : 0;
        __syncthreads();
        ss[tid] += t;
        __syncthreads();
    }
    if (i < NN) {
        int excl = ss[tid] - c + g_bsum[blockIdx.x];
        g_offsets[i] = excl;
        g_cursor[i] = excl;
    }
}

__global__ void fill_kernel(const int* __restrict__ edst) {
    int e = blockIdx.x * blockDim.x + threadIdx.x;
    if (e < EN) {
        int d = edst[e];
        int p = atomicAdd(&g_cursor[d], 1);
        g_csr[p] = e;
    }
}

// ---------------- aggregation + residual + LayerNorm (bf16 gathers, 2 ch/thread) --------
__global__ __launch_bounds__(128) void aggregate_ln_kernel(
    const int* __restrict__ esrc,
    const float* __restrict__ gamma,
    const float* __restrict__ beta,
    float* __restrict__ out)
{
    int i = blockIdx.x;
    int tid = threadIdx.x;        // 0..127, channels 2*tid, 2*tid+1
    int h = tid >> 4;             // head of this channel pair
    __shared__ int   ssrc[64];
    __shared__ float sw[64 * 8];
    __shared__ float sred[4], sred2[4];

    int p0 = g_offsets[i], p1 = g_offsets[i + 1];
    float ax = 0.f, ay = 0.f;

    for (int base = p0; base < p1; base += 64) {
        int n = min(64, p1 - base);
        __syncthreads();
        if (tid < n) {
            int e = __ldg(&g_csr[base + tid]);
            ssrc[tid] = __ldg(&esrc[e]);
            const float* wp = g_w + (size_t)e * HH;
            float4 w0 = __ldg((const float4*)wp);
            float4 w1 = __ldg((const float4*)(wp + 4));
            *(float4*)&sw[tid * 8]     = w0;
            *(float4*)&sw[tid * 8 + 4] = w1;
        }
        __syncthreads();
        int j = 0;
        for (; j + 4 <= n; j += 4) {
            int s0 = ssrc[j], s1 = ssrc[j + 1], s2 = ssrc[j + 2], s3 = ssrc[j + 3];
            float w0 = sw[j * 8 + h], w1 = sw[(j + 1) * 8 + h];
            float w2 = sw[(j + 2) * 8 + h], w3 = sw[(j + 3) * 8 + h];
            uint32_t x0 = __ldg(&g_xlh[(size_t)s0 * 128 + tid]);
            uint32_t x1 = __ldg(&g_xlh[(size_t)s1 * 128 + tid]);
            uint32_t x2 = __ldg(&g_xlh[(size_t)s2 * 128 + tid]);
            uint32_t x3 = __ldg(&g_xlh[(size_t)s3 * 128 + tid]);
            float2 f0 = unpk(x0), f1 = unpk(x1), f2 = unpk(x2), f3 = unpk(x3);
            ax += f0.x * w0; ay += f0.y * w0;
            ax += f1.x * w1; ay += f1.y * w1;
            ax += f2.x * w2; ay += f2.y * w2;
            ax += f3.x * w3; ay += f3.y * w3;
        }
        for (; j < n; j++) {
            float2 f = unpk(__ldg(&g_xlh[(size_t)ssrc[j] * 128 + tid]));
            float w = sw[j * 8 + h];
            ax += f.x * w; ay += f.y * w;
        }
    }

    float den = __ldg(&g_denom[(size_t)i * HH + h]);
    float invd = (den > 0.f) ? (1.f / den) : 0.f;
    float2 bb = *(const float2*)(g_base + (size_t)i * DD + tid * 2);
    float vx = ax * invd + bb.x;
    float vy = ay * invd + bb.y;

    float s1 = vx + vy, s2 = vx * vx + vy * vy;
#pragma unroll
    for (int off = 16; off; off >>= 1) {
        s1 += __shfl_down_sync(0xffffffffu, s1, off);
        s2 += __shfl_down_sync(0xffffffffu, s2, off);
    }
    if ((tid & 31) == 0) { sred[tid >> 5] = s1; sred2[tid >> 5] = s2; }
    __syncthreads();
    if (tid == 0) {
        float a = 0.f, b = 0.f;
#pragma unroll
        for (int j = 0; j < 4; j++) { a += sred[j]; b += sred2[j]; }
        float mu = a * (1.f / DD);
        float var = b * (1.f / DD) - mu * mu;
        sred[0] = mu;
        sred2[0] = rsqrtf(fmaxf(var, 0.f) + 1e-5f);
    }
    __syncthreads();
    float mu = sred[0], rstd = sred2[0];
    float2 gm = *(const float2*)(gamma + tid * 2);
    float2 bt = *(const float2*)(beta + tid * 2);
    float2 o;
    o.x = (vx - mu) * rstd * gm.x + bt.x;
    o.y = (vy - mu) * rstd * gm.y + bt.y;
    *(float2*)(out + (size_t)i * DD + tid * 2) = o;
}

// ---------------- launch ----------------
extern "C" void kernel_launch(void* const* d_in, const int* in_sizes, int n_in,
                              void* d_out, int out_size)
{
    const float *x, *ea, *Wl, *bl, *Wr, *br, *We, *att, *Wres, *bias, *gamma, *beta;
    const int* eidx;

    if (n_in >= 13 && in_sizes[2] == 2 * EN) {
        x     = (const float*)d_in[0];
        ea    = (const float*)d_in[1];
        eidx  = (const int*)  d_in[2];
        Wl    = (const float*)d_in[3];
        bl    = (const float*)d_in[4];
        Wr    = (const float*)d_in[5];
        br    = (const float*)d_in[6];
        We    = (const float*)d_in[7];
        att   = (const float*)d_in[8];
        Wres  = (const float*)d_in[9];
        bias  = (const float*)d_in[10];
        gamma = (const float*)d_in[11];
        beta  = (const float*)d_in[12];
    } else {
        x     = (const float*)d_in[0];
        ea    = (const float*)d_in[1];
        Wl    = (const float*)d_in[2];
        bl    = (const float*)d_in[3];
        Wr    = (const float*)d_in[4];
        br    = (const float*)d_in[5];
        We    = (const float*)d_in[6];
        att   = (const float*)d_in[7];
        Wres  = (const float*)d_in[8];
        bias  = (const float*)d_in[9];
        gamma = (const float*)d_in[10];
        beta  = (const float*)d_in[11];
        eidx  = (const int*)  d_in[12];
    }
    const int* esrc = eidx;
    const int* edst = eidx + EN;
    float* out = (float*)d_out;

    cudaFuncSetAttribute(node_gemm_tc, cudaFuncAttributeMaxDynamicSharedMemorySize, NODE_SMEM);
    cudaFuncSetAttribute(edge_kernel_tc, cudaFuncAttributeMaxDynamicSharedMemorySize, EDGE_SMEM);

    zero_kernel<<<(NN * HH + 255) / 256, 256>>>();
    node_gemm_tc<<<dim3((NN + 127) / 128, 6), 256, NODE_SMEM>>>(x, Wl, bl, Wr, br, Wres, bias);
    edge_kernel_tc<<<EN / 128, 256, EDGE_SMEM>>>(ea, We, att, esrc, edst);
    scan_part<<<SCAN_BLOCKS, 256>>>();
    scan_mid<<<1, 256>>>();
    scan_final<<<SCAN_BLOCKS, 256>>>();
    fill_kernel<<<(EN + 255) / 256, 256>>>(edst);
    aggregate_ln_kernel<<<NN, 128>>>(esrc, gamma, beta, out);
}

// round 14
// speedup vs baseline: 4.3299x; 1.0724x over previous
#include <cuda_runtime.h>
#include <cuda_bf16.h>
#include <cstdint>

#define NN   50000
#define EN   800000
#define DD   256
#define HH   8
#define DE   64
#define NEG  0.2f

// ---------------- device scratch ----------------
__device__ float    g_base[(size_t)NN * DD];
__device__ uint32_t g_xlh[(size_t)NN * (DD / 2)];   // bf16x2 xl
__device__ uint32_t g_xrh[(size_t)NN * (DD / 2)];   // bf16x2 xr
__device__ float    g_w[(size_t)EN * HH];
__device__ float    g_denom[(size_t)NN * HH];
__device__ int      g_counts[NN];
__device__ int      g_offsets[NN + 1];
__device__ int      g_cursor[NN];
__device__ int      g_csr[EN];
__device__ int      g_bsum[256];

// ---------------- helpers ----------------
__device__ __forceinline__ uint32_t s2u(const void* p) {
    uint32_t a;
    asm("{ .reg .u64 t; cvta.to.shared.u64 t, %1; cvt.u32.u64 %0, t; }" : "=r"(a) : "l"(p));
    return a;
}
__device__ __forceinline__ void ldsm_x4(uint32_t* r, uint32_t addr) {
    asm volatile("ldmatrix.sync.aligned.m8n8.x4.shared.b16 {%0,%1,%2,%3}, [%4];"
        : "=r"(r[0]), "=r"(r[1]), "=r"(r[2]), "=r"(r[3]) : "r"(addr));
}
__device__ __forceinline__ void mma16816(float* c, const uint32_t* a, uint32_t b0, uint32_t b1) {
    asm volatile("mma.sync.aligned.m16n8k16.row.col.f32.bf16.bf16.f32 "
        "{%0,%1,%2,%3}, {%4,%5,%6,%7}, {%8,%9}, {%0,%1,%2,%3};"
        : "+f"(c[0]), "+f"(c[1]), "+f"(c[2]), "+f"(c[3])
        : "r"(a[0]), "r"(a[1]), "r"(a[2]), "r"(a[3]), "r"(b0), "r"(b1));
}
__device__ __forceinline__ uint2 pack4(float4 v, bool lo) {
    __nv_bfloat16 h0 = __float2bfloat16(v.x), h1 = __float2bfloat16(v.y);
    __nv_bfloat16 h2 = __float2bfloat16(v.z), h3 = __float2bfloat16(v.w);
    if (lo) {
        h0 = __float2bfloat16(v.x - __bfloat162float(h0));
        h1 = __float2bfloat16(v.y - __bfloat162float(h1));
        h2 = __float2bfloat16(v.z - __bfloat162float(h2));
        h3 = __float2bfloat16(v.w - __bfloat162float(h3));
    }
    uint2 r;
    r.x = ((uint32_t)__bfloat16_as_ushort(h1) << 16) | __bfloat16_as_ushort(h0);
    r.y = ((uint32_t)__bfloat16_as_ushort(h3) << 16) | __bfloat16_as_ushort(h2);
    return r;
}
__device__ __forceinline__ uint32_t bfpack2(float a, float b) {
    __nv_bfloat162 h;
    h.x = __float2bfloat16(a);
    h.y = __float2bfloat16(b);
    return *(uint32_t*)&h;
}
__device__ __forceinline__ float2 unpk(uint32_t u) {
    __nv_bfloat162 h = *(__nv_bfloat162*)&u;
    return __bfloat1622float2(h);
}

// fragment address helpers (pitch 40 bf16 per row)
__device__ __forceinline__ uint32_t a_frag_addr(uint32_t base, int mrow0, int kk, int lane) {
    int row = mrow0 + (lane & 15);
    int col = kk + ((lane >> 4) << 3);
    return base + (uint32_t)(row * 40 + col) * 2;
}
__device__ __forceinline__ uint32_t b_frag_addr(uint32_t base, int n0, int kk, int lane) {
    int row = n0 + (lane & 7) + ((lane >> 4) << 3);
    int col = kk + (((lane >> 3) & 1) << 3);
    return base + (uint32_t)(row * 40 + col) * 2;
}

__device__ __forceinline__ void mma_chunk1(
    float acc[2][8][4], uint32_t ab, uint32_t bb, int mwarp, int nwarp, int lane)
{
#pragma unroll
    for (int ks = 0; ks < 32; ks += 16) {
        uint32_t af[2][4];
        ldsm_x4(af[0], a_frag_addr(ab, mwarp * 32, ks, lane));
        ldsm_x4(af[1], a_frag_addr(ab, mwarp * 32 + 16, ks, lane));
#pragma unroll
        for (int ng = 0; ng < 4; ng++) {
            uint32_t bf[4];
            ldsm_x4(bf, b_frag_addr(bb, nwarp * 64 + ng * 16, ks, lane));
            mma16816(acc[0][2 * ng + 0], af[0], bf[0], bf[1]);
            mma16816(acc[0][2 * ng + 1], af[0], bf[2], bf[3]);
            mma16816(acc[1][2 * ng + 0], af[1], bf[0], bf[1]);
            mma16816(acc[1][2 * ng + 1], af[1], bf[2], bf[3]);
        }
    }
}

// ---------------- K0: zero ----------------
__global__ void zero_kernel() {
    int i = blockIdx.x * blockDim.x + threadIdx.x;
    if (i < NN * HH) g_denom[i] = 0.f;
    if (i < NN) g_counts[i] = 0;
    if (i == 0) g_offsets[NN] = EN;
}

// ---------------- node GEMM (HMMA, reg-prefetch pipeline) ----------------
// mat 0/1 (xl, xr): 2-pass split (AhBh + AlBh), bf16 output only.
// mat 2   (base)  : 3-pass split, fp32 output.
#define NA_HI 0u
#define NA_LO 10240u
#define NB_HI 20480u
#define NB_LO 30720u
#define NODE_SMEM 40960

__global__ __launch_bounds__(256, 1) void node_gemm_tc(
    const float* __restrict__ x,
    const float* __restrict__ Wl, const float* __restrict__ bl,
    const float* __restrict__ Wr, const float* __restrict__ br,
    const float* __restrict__ Wres, const float* __restrict__ bres)
{
    extern __shared__ char smem[];
    uint32_t sb = s2u(smem);
    int tid = threadIdx.x, lane = tid & 31, wid = tid >> 5;
    int mwarp = wid >> 1, nwarp = wid & 1;
    int m0 = blockIdx.x * 128;
    int mat = blockIdx.y >> 1;
    int nhalf = blockIdx.y & 1;
    bool isBase = (mat == 2);

    const float* W  = (mat == 0) ? Wl : ((mat == 1) ? Wr : Wres);
    const float* bv = (mat == 0) ? bl : ((mat == 1) ? br : bres);
    uint32_t* outh  = (mat == 0) ? g_xlh : g_xrh;
    int ncol0 = nhalf * 128;

    int srow[4], skq[4];
    const float* aptr[4];
    const float* bptr[4];
#pragma unroll
    for (int it = 0; it < 4; it++) {
        int i = tid + it * 256;
        int r = i >> 3, kq = (i & 7) << 2;
        srow[it] = r; skq[it] = kq;
        int m = m0 + r; if (m >= NN) m = NN - 1;
        aptr[it] = x + (size_t)m * DD + kq;
        bptr[it] = W + (size_t)(ncol0 + r) * DD + kq;
    }

    float acc[2][8][4];
#pragma unroll
    for (int i = 0; i < 2; i++)
#pragma unroll
        for (int j = 0; j < 8; j++)
#pragma unroll
            for (int k = 0; k < 4; k++) acc[i][j][k] = 0.f;

    float4 ra[4], rb[4];
#pragma unroll
    for (int it = 0; it < 4; it++) {
        ra[it] = __ldg((const float4*)(aptr[it]));
        rb[it] = __ldg((const float4*)(bptr[it]));
    }

    for (int c = 0; c < 8; c++) {
        __syncthreads();
#pragma unroll
        for (int it = 0; it < 4; it++) {
            uint32_t off = (uint32_t)(srow[it] * 40 + skq[it]) * 2;
            *(uint2*)(smem + NA_HI + off) = pack4(ra[it], false);
            *(uint2*)(smem + NA_LO + off) = pack4(ra[it], true);
            *(uint2*)(smem + NB_HI + off) = pack4(rb[it], false);
            if (isBase)
                *(uint2*)(smem + NB_LO + off) = pack4(rb[it], true);
        }
        __syncthreads();
        if (c < 7) {
            int k0 = (c + 1) * 32;
#pragma unroll
            for (int it = 0; it < 4; it++) {
                ra[it] = __ldg((const float4*)(aptr[it] + k0));
                rb[it] = __ldg((const float4*)(bptr[it] + k0));
            }
        }
        mma_chunk1(acc, sb + NA_HI, sb + NB_HI, mwarp, nwarp, lane);
        mma_chunk1(acc, sb + NA_LO, sb + NB_HI, mwarp, nwarp, lane);
        if (isBase)
            mma_chunk1(acc, sb + NA_HI, sb + NB_LO, mwarp, nwarp, lane);
    }

#pragma unroll
    for (int mt = 0; mt < 2; mt++) {
        int row = m0 + mwarp * 32 + mt * 16 + (lane >> 2);
#pragma unroll
        for (int nt = 0; nt < 8; nt++) {
            int col = ncol0 + nwarp * 64 + nt * 8 + ((lane & 3) << 1);
            float b0 = __ldg(&bv[col]), b1 = __ldg(&bv[col + 1]);
            float v0 = acc[mt][nt][0] + b0, v1 = acc[mt][nt][1] + b1;
            float v2 = acc[mt][nt][2] + b0, v3 = acc[mt][nt][3] + b1;
            if (isBase) {
                if (row < NN) {
                    float2 v = {v0, v1};
                    *(float2*)(g_base + (size_t)row * DD + col) = v;
                }
                if (row + 8 < NN) {
                    float2 v = {v2, v3};
                    *(float2*)(g_base + (size_t)(row + 8) * DD + col) = v;
                }
            } else {
                if (row < NN)
                    outh[(size_t)row * 128 + (col >> 1)] = bfpack2(v0, v1);
                if (row + 8 < NN)
                    outh[(size_t)(row + 8) * 128 + (col >> 1)] = bfpack2(v2, v3);
            }
        }
    }
}

// ---------------- edge kernel: fused ee GEMM (single-pass bf16) + logits + hist ----------------
#define EE_OFF  0u                  // 128 x 133 u32 = 68096 B
#define EA_OFF  68096u              // 2 chunks x 128 x 40 bf16 = 20480 B
#define EB_OFF  (EA_OFF + 20480u)
#define EIDX    (EB_OFF + 20480u)
#define EDGE_SMEM (EIDX + 1024u)    // 110080 -> 2 CTAs/SM

__global__ __launch_bounds__(256, 2) void edge_kernel_tc(
    const float* __restrict__ ea,
    const float* __restrict__ We,
    const float* __restrict__ att,
    const int* __restrict__ esrc,
    const int* __restrict__ edst)
{
    extern __shared__ char smem[];
    uint32_t sb = s2u(smem);
    int tid = threadIdx.x, lane = tid & 31, wid = tid >> 5;
    int mwarp = wid >> 1, nwarp = wid & 1;
    int e0 = blockIdx.x * 128;
    int* sSrc = (int*)(smem + EIDX);
    int* sDst = sSrc + 128;
    uint32_t* ee32 = (uint32_t*)(smem + EE_OFF);

    if (tid < 128) {
        int s = esrc[e0 + tid];
        int d = edst[e0 + tid];
        sSrc[tid] = s;
        sDst[tid] = d;
        atomicAdd(&g_counts[d], 1);   // fused histogram
    }

#pragma unroll
    for (int it = 0; it < 8; it++) {
        int i = tid + it * 256;
        int r = i >> 4, kq = (i & 15) << 2;
        float4 v = __ldg((const float4*)(ea + (size_t)(e0 + r) * DE + kq));
        int ch = kq >> 5, kc = kq & 31;
        uint32_t off = (uint32_t)(ch * 5120 + r * 40 + kc) * 2;
        *(uint2*)(smem + EA_OFF + off) = pack4(v, false);
    }

    for (int nh = 0; nh < 2; nh++) {
        if (nh) __syncthreads();
#pragma unroll
        for (int it = 0; it < 8; it++) {
            int i = tid + it * 256;
            int r = i >> 4, kq = (i & 15) << 2;
            float4 v = __ldg((const float4*)(We + (size_t)(nh * 128 + r) * DE + kq));
            int ch = kq >> 5, kc = kq & 31;
            uint32_t off = (uint32_t)(ch * 5120 + r * 40 + kc) * 2;
            *(uint2*)(smem + EB_OFF + off) = pack4(v, false);
        }
        __syncthreads();

        float acc[2][8][4];
#pragma unroll
        for (int i = 0; i < 2; i++)
#pragma unroll
            for (int j = 0; j < 8; j++)
#pragma unroll
                for (int k = 0; k < 4; k++) acc[i][j][k] = 0.f;

#pragma unroll
        for (int c = 0; c < 2; c++)
            mma_chunk1(acc, sb + EA_OFF + c * 10240, sb + EB_OFF + c * 10240,
                       mwarp, nwarp, lane);

#pragma unroll
        for (int mt = 0; mt < 2; mt++) {
            int el = mwarp * 32 + mt * 16 + (lane >> 2);
#pragma unroll
            for (int nt = 0; nt < 8; nt++) {
                int w = nh * 64 + nwarp * 32 + nt * 4 + (lane & 3);
                ee32[el * 133 + w]       = bfpack2(acc[mt][nt][0], acc[mt][nt][1]);
                ee32[(el + 8) * 133 + w] = bfpack2(acc[mt][nt][2], acc[mt][nt][3]);
            }
        }
    }
    __syncthreads();

    // logit phase: quad of lanes per edge; xl/xr read as bf16x2
    int q = tid & 3;
    for (int rep = 0; rep < 2; rep++) {
        int el = (tid >> 2) + rep * 64;
        int s = sSrc[el];
        int d = sDst[el];
        const uint32_t* xlp = g_xlh + (size_t)s * 128;
        const uint32_t* xrp = g_xrh + (size_t)d * 128;
        uint32_t eeb = el * 133 + q * 4;
#pragma unroll
        for (int h = 0; h < 8; h++) {
            int cb  = h * 32 + q * 8;
            int cb2 = h * 16 + q * 4;
            uint4 U = __ldg((const uint4*)(xlp + cb2));
            uint4 R = __ldg((const uint4*)(xrp + cb2));
            float2 u0 = unpk(U.x), u1 = unpk(U.y), u2 = unpk(U.z), u3 = unpk(U.w);
            float2 r0 = unpk(R.x), r1 = unpk(R.y), r2 = unpk(R.z), r3 = unpk(R.w);
            float2 f0 = unpk(ee32[eeb + h * 16 + 0]);
            float2 f1 = unpk(ee32[eeb + h * 16 + 1]);
            float2 f2 = unpk(ee32[eeb + h * 16 + 2]);
            float2 f3 = unpk(ee32[eeb + h * 16 + 3]);
            float4 a0 = __ldg((const float4*)(att + cb));
            float4 a1 = __ldg((const float4*)(att + cb + 4));
            float p = 0.f, z;
            z = u0.x + r0.x + f0.x; z = (z > 0.f) ? z : NEG * z; p += z * a0.x;
            z = u0.y + r0.y + f0.y; z = (z > 0.f) ? z : NEG * z; p += z * a0.y;
            z = u1.x + r1.x + f1.x; z = (z > 0.f) ? z : NEG * z; p += z * a0.z;
            z = u1.y + r1.y + f1.y; z = (z > 0.f) ? z : NEG * z; p += z * a0.w;
            z = u2.x + r2.x + f2.x; z = (z > 0.f) ? z : NEG * z; p += z * a1.x;
            z = u2.y + r2.y + f2.y; z = (z > 0.f) ? z : NEG * z; p += z * a1.y;
            z = u3.x + r3.x + f3.x; z = (z > 0.f) ? z : NEG * z; p += z * a1.z;
            z = u3.y + r3.y + f3.y; z = (z > 0.f) ? z : NEG * z; p += z * a1.w;
            p += __shfl_xor_sync(0xffffffffu, p, 1);
            p += __shfl_xor_sync(0xffffffffu, p, 2);
            if (q == 0) {
                float w = __expf(p);
                g_w[(size_t)(e0 + el) * HH + h] = w;
                atomicAdd(&g_denom[(size_t)d * HH + h], w);
            }
        }
    }
}

// ---------------- scan: 3-kernel device-wide exclusive scan of g_counts ----------------
#define SCAN_BLOCKS ((NN + 255) / 256)   // 196

__global__ __launch_bounds__(256) void scan_part() {
    int i = blockIdx.x * 256 + threadIdx.x;
    int c = (i < NN) ? g_counts[i] : 0;
    int v = c;
#pragma unroll
    for (int off = 16; off; off >>= 1) v += __shfl_down_sync(0xffffffffu, v, off);
    __shared__ int ws[8];
    if ((threadIdx.x & 31) == 0) ws[threadIdx.x >> 5] = v;
    __syncthreads();
    if (threadIdx.x == 0) {
        int s = 0;
#pragma unroll
        for (int j = 0; j < 8; j++) s += ws[j];
        g_bsum[blockIdx.x] = s;
    }
}

__global__ __launch_bounds__(256) void scan_mid() {
    __shared__ int ss[256];
    int tid = threadIdx.x;
    int v = (tid < SCAN_BLOCKS) ? g_bsum[tid] : 0;
    ss[tid] = v;
    __syncthreads();
#pragma unroll
    for (int off = 1; off < 256; off <<= 1) {
        int t = (tid >= off) ? ss[tid - off] : 0;
        __syncthreads();
        ss[tid] += t;
        __syncthreads();
    }
    if (tid < SCAN_BLOCKS) g_bsum[tid] = ss[tid] - v;   // exclusive
}

__global__ __launch_bounds__(256) void scan_final() {
    __shared__ int ss[256];
    int tid = threadIdx.x;
    int i = blockIdx.x * 256 + tid;
    int c = (i < NN) ? g_counts[i] : 0;
    ss[tid] = c;
    __syncthreads();
#pragma unroll
    for (int off = 1; off < 256; off <<= 1) {
        int t = (tid >= off) ? ss[tid - off] : 0;
        __syncthreads();
        ss[tid] += t;
        __syncthreads();
    }
    if (i < NN) {
        int excl = ss[tid] - c + g_bsum[blockIdx.x];
        g_offsets[i] = excl;
        g_cursor[i] = excl;
    }
}

__global__ void fill_kernel(const int* __restrict__ edst) {
    int e = blockIdx.x * blockDim.x + threadIdx.x;
    if (e < EN) {
        int d = edst[e];
        int p = atomicAdd(&g_cursor[d], 1);
        g_csr[p] = e;
    }
}

// ---------------- aggregation + residual + LayerNorm (warp-per-node, no barriers) ------
__device__ __forceinline__ void addw(float* acc, uint4 X, float w) {
    float2 f0 = unpk(X.x), f1 = unpk(X.y), f2 = unpk(X.z), f3 = unpk(X.w);
    acc[0] += f0.x * w; acc[1] += f0.y * w;
    acc[2] += f1.x * w; acc[3] += f1.y * w;
    acc[4] += f2.x * w; acc[5] += f2.y * w;
    acc[6] += f3.x * w; acc[7] += f3.y * w;
}

__global__ __launch_bounds__(256) void aggregate_ln_kernel(
    const int* __restrict__ esrc,
    const float* __restrict__ gamma,
    const float* __restrict__ beta,
    float* __restrict__ out)
{
    int lane = threadIdx.x & 31;
    int i = blockIdx.x * 8 + (threadIdx.x >> 5);
    if (i >= NN) return;
    int h = lane >> 2;                 // head of this lane's 8 channels
    int p0 = g_offsets[i], p1 = g_offsets[i + 1];

    float acc[8];
#pragma unroll
    for (int k = 0; k < 8; k++) acc[k] = 0.f;

    for (int b0 = p0; b0 < p1; b0 += 32) {
        int n = min(32, p1 - b0);
        int e = 0, s = 0;
        if (lane < n) {
            e = __ldg(&g_csr[b0 + lane]);
            s = __ldg(&esrc[e]);
        }
        int j = 0;
        for (; j + 4 <= n; j += 4) {
            int e0 = __shfl_sync(0xffffffffu, e, j + 0), s0 = __shfl_sync(0xffffffffu, s, j + 0);
            int e1 = __shfl_sync(0xffffffffu, e, j + 1), s1 = __shfl_sync(0xffffffffu, s, j + 1);
            int e2 = __shfl_sync(0xffffffffu, e, j + 2), s2 = __shfl_sync(0xffffffffu, s, j + 2);
            int e3 = __shfl_sync(0xffffffffu, e, j + 3), s3 = __shfl_sync(0xffffffffu, s, j + 3);
            float w0 = __ldg(&g_w[(size_t)e0 * HH + h]);
            float w1 = __ldg(&g_w[(size_t)e1 * HH + h]);
            float w2 = __ldg(&g_w[(size_t)e2 * HH + h]);
            float w3 = __ldg(&g_w[(size_t)e3 * HH + h]);
            uint4 X0 = __ldg((const uint4*)(g_xlh + (size_t)s0 * 128) + lane);
            uint4 X1 = __ldg((const uint4*)(g_xlh + (size_t)s1 * 128) + lane);
            uint4 X2 = __ldg((const uint4*)(g_xlh + (size_t)s2 * 128) + lane);
            uint4 X3 = __ldg((const uint4*)(g_xlh + (size_t)s3 * 128) + lane);
            addw(acc, X0, w0);
            addw(acc, X1, w1);
            addw(acc, X2, w2);
            addw(acc, X3, w3);
        }
        for (; j < n; j++) {
            int ej = __shfl_sync(0xffffffffu, e, j), sj = __shfl_sync(0xffffffffu, s, j);
            float wj = __ldg(&g_w[(size_t)ej * HH + h]);
            uint4 X = __ldg((const uint4*)(g_xlh + (size_t)sj * 128) + lane);
            addw(acc, X, wj);
        }
    }

    float den = __ldg(&g_denom[(size_t)i * HH + h]);
    float invd = (den > 0.f) ? (1.f / den) : 0.f;
    const float* bp = g_base + (size_t)i * DD + lane * 8;
    float4 bb0 = __ldg((const float4*)bp);
    float4 bb1 = __ldg((const float4*)(bp + 4));
    float v[8];
    v[0] = acc[0] * invd + bb0.x; v[1] = acc[1] * invd + bb0.y;
    v[2] = acc[2] * invd + bb0.z; v[3] = acc[3] * invd + bb0.w;
    v[4] = acc[4] * invd + bb1.x; v[5] = acc[5] * invd + bb1.y;
    v[6] = acc[6] * invd + bb1.z; v[7] = acc[7] * invd + bb1.w;

    float s1 = 0.f, s2 = 0.f;
#pragma unroll
    for (int k = 0; k < 8; k++) { s1 += v[k]; s2 += v[k] * v[k]; }
#pragma unroll
    for (int off = 16; off; off >>= 1) {
        s1 += __shfl_xor_sync(0xffffffffu, s1, off);
        s2 += __shfl_xor_sync(0xffffffffu, s2, off);
    }
    float mu = s1 * (1.f / DD);
    float var = s2 * (1.f / DD) - mu * mu;
    float rstd = rsqrtf(fmaxf(var, 0.f) + 1e-5f);

    const float* gp = gamma + lane * 8;
    const float* btp = beta + lane * 8;
    float4 g0 = __ldg((const float4*)gp), g1 = __ldg((const float4*)(gp + 4));
    float4 t0 = __ldg((const float4*)btp), t1 = __ldg((const float4*)(btp + 4));
    float* op = out + (size_t)i * DD + lane * 8;
    float4 o0, o1;
    o0.x = (v[0] - mu) * rstd * g0.x + t0.x;
    o0.y = (v[1] - mu) * rstd * g0.y + t0.y;
    o0.z = (v[2] - mu) * rstd * g0.z + t0.z;
    o0.w = (v[3] - mu) * rstd * g0.w + t0.w;
    o1.x = (v[4] - mu) * rstd * g1.x + t1.x;
    o1.y = (v[5] - mu) * rstd * g1.y + t1.y;
    o1.z = (v[6] - mu) * rstd * g1.z + t1.z;
    o1.w = (v[7] - mu) * rstd * g1.w + t1.w;
    *(float4*)op = o0;
    *(float4*)(op + 4) = o1;
}

// ---------------- launch ----------------
extern "C" void kernel_launch(void* const* d_in, const int* in_sizes, int n_in,
                              void* d_out, int out_size)
{
    const float *x, *ea, *Wl, *bl, *Wr, *br, *We, *att, *Wres, *bias, *gamma, *beta;
    const int* eidx;

    if (n_in >= 13 && in_sizes[2] == 2 * EN) {
        x     = (const float*)d_in[0];
        ea    = (const float*)d_in[1];
        eidx  = (const int*)  d_in[2];
        Wl    = (const float*)d_in[3];
        bl    = (const float*)d_in[4];
        Wr    = (const float*)d_in[5];
        br    = (const float*)d_in[6];
        We    = (const float*)d_in[7];
        att   = (const float*)d_in[8];
        Wres  = (const float*)d_in[9];
        bias  = (const float*)d_in[10];
        gamma = (const float*)d_in[11];
        beta  = (const float*)d_in[12];
    } else {
        x     = (const float*)d_in[0];
        ea    = (const float*)d_in[1];
        Wl    = (const float*)d_in[2];
        bl    = (const float*)d_in[3];
        Wr    = (const float*)d_in[4];
        br    = (const float*)d_in[5];
        We    = (const float*)d_in[6];
        att   = (const float*)d_in[7];
        Wres  = (const float*)d_in[8];
        bias  = (const float*)d_in[9];
        gamma = (const float*)d_in[10];
        beta  = (const float*)d_in[11];
        eidx  = (const int*)  d_in[12];
    }
    const int* esrc = eidx;
    const int* edst = eidx + EN;
    float* out = (float*)d_out;

    cudaFuncSetAttribute(node_gemm_tc, cudaFuncAttributeMaxDynamicSharedMemorySize, NODE_SMEM);
    cudaFuncSetAttribute(edge_kernel_tc, cudaFuncAttributeMaxDynamicSharedMemorySize, EDGE_SMEM);

    zero_kernel<<<(NN * HH + 255) / 256, 256>>>();
    node_gemm_tc<<<dim3((NN + 127) / 128, 6), 256, NODE_SMEM>>>(x, Wl, bl, Wr, br, Wres, bias);
    edge_kernel_tc<<<EN / 128, 256, EDGE_SMEM>>>(ea, We, att, esrc, edst);
    scan_part<<<SCAN_BLOCKS, 256>>>();
    scan_mid<<<1, 256>>>();
    scan_final<<<SCAN_BLOCKS, 256>>>();
    fill_kernel<<<(EN + 255) / 256, 256>>>(edst);
    aggregate_ln_kernel<<<(NN + 7) / 8, 256>>>(esrc, gamma, beta, out);
}

// round 16
// speedup vs baseline: 4.6015x; 1.0627x over previous
#include <cuda_runtime.h>
#include <cuda_bf16.h>
#include <cstdint>

#define NN   50000
#define EN   800000
#define DD   256
#define HH   8
#define DE   64
#define NEG  0.2f

// ---------------- device scratch ----------------
__device__ float    g_base[(size_t)NN * DD];
__device__ uint32_t g_xlh[(size_t)NN * (DD / 2)];   // bf16x2 xl
__device__ uint32_t g_xrh[(size_t)NN * (DD / 2)];   // bf16x2 xr
__device__ float    g_w[(size_t)EN * HH];           // CSR-ordered softmax numerators
__device__ int      g_counts[NN];
__device__ int      g_offsets[NN + 1];
__device__ int      g_cursor[NN];
__device__ int      g_csr[EN];                      // CSR slot -> edge id
__device__ int2     g_sd[EN];                       // CSR slot -> (src, dst)
__device__ int      g_bsum[256];

// ---------------- helpers ----------------
__device__ __forceinline__ uint32_t s2u(const void* p) {
    uint32_t a;
    asm("{ .reg .u64 t; cvta.to.shared.u64 t, %1; cvt.u32.u64 %0, t; }" : "=r"(a) : "l"(p));
    return a;
}
__device__ __forceinline__ void ldsm_x4(uint32_t* r, uint32_t addr) {
    asm volatile("ldmatrix.sync.aligned.m8n8.x4.shared.b16 {%0,%1,%2,%3}, [%4];"
        : "=r"(r[0]), "=r"(r[1]), "=r"(r[2]), "=r"(r[3]) : "r"(addr));
}
__device__ __forceinline__ void mma16816(float* c, const uint32_t* a, uint32_t b0, uint32_t b1) {
    asm volatile("mma.sync.aligned.m16n8k16.row.col.f32.bf16.bf16.f32 "
        "{%0,%1,%2,%3}, {%4,%5,%6,%7}, {%8,%9}, {%0,%1,%2,%3};"
        : "+f"(c[0]), "+f"(c[1]), "+f"(c[2]), "+f"(c[3])
        : "r"(a[0]), "r"(a[1]), "r"(a[2]), "r"(a[3]), "r"(b0), "r"(b1));
}
__device__ __forceinline__ uint2 pack4(float4 v, bool lo) {
    __nv_bfloat16 h0 = __float2bfloat16(v.x), h1 = __float2bfloat16(v.y);
    __nv_bfloat16 h2 = __float2bfloat16(v.z), h3 = __float2bfloat16(v.w);
    if (lo) {
        h0 = __float2bfloat16(v.x - __bfloat162float(h0));
        h1 = __float2bfloat16(v.y - __bfloat162float(h1));
        h2 = __float2bfloat16(v.z - __bfloat162float(h2));
        h3 = __float2bfloat16(v.w - __bfloat162float(h3));
    }
    uint2 r;
    r.x = ((uint32_t)__bfloat16_as_ushort(h1) << 16) | __bfloat16_as_ushort(h0);
    r.y = ((uint32_t)__bfloat16_as_ushort(h3) << 16) | __bfloat16_as_ushort(h2);
    return r;
}
__device__ __forceinline__ uint32_t bfpack2(float a, float b) {
    __nv_bfloat162 h;
    h.x = __float2bfloat16(a);
    h.y = __float2bfloat16(b);
    return *(uint32_t*)&h;
}
__device__ __forceinline__ float2 unpk(uint32_t u) {
    __nv_bfloat162 h = *(__nv_bfloat162*)&u;
    return __bfloat1622float2(h);
}

// fragment address helpers (pitch 40 bf16 per row)
__device__ __forceinline__ uint32_t a_frag_addr(uint32_t base, int mrow0, int kk, int lane) {
    int row = mrow0 + (lane & 15);
    int col = kk + ((lane >> 4) << 3);
    return base + (uint32_t)(row * 40 + col) * 2;
}
__device__ __forceinline__ uint32_t b_frag_addr(uint32_t base, int n0, int kk, int lane) {
    int row = n0 + (lane & 7) + ((lane >> 4) << 3);
    int col = kk + (((lane >> 3) & 1) << 3);
    return base + (uint32_t)(row * 40 + col) * 2;
}

__device__ __forceinline__ void mma_chunk1(
    float acc[2][8][4], uint32_t ab, uint32_t bb, int mwarp, int nwarp, int lane)
{
#pragma unroll
    for (int ks = 0; ks < 32; ks += 16) {
        uint32_t af[2][4];
        ldsm_x4(af[0], a_frag_addr(ab, mwarp * 32, ks, lane));
        ldsm_x4(af[1], a_frag_addr(ab, mwarp * 32 + 16, ks, lane));
#pragma unroll
        for (int ng = 0; ng < 4; ng++) {
            uint32_t bf[4];
            ldsm_x4(bf, b_frag_addr(bb, nwarp * 64 + ng * 16, ks, lane));
            mma16816(acc[0][2 * ng + 0], af[0], bf[0], bf[1]);
            mma16816(acc[0][2 * ng + 1], af[0], bf[2], bf[3]);
            mma16816(acc[1][2 * ng + 0], af[1], bf[0], bf[1]);
            mma16816(acc[1][2 * ng + 1], af[1], bf[2], bf[3]);
        }
    }
}

// ---------------- K0: zero counts ----------------
__global__ void zero_kernel() {
    int i = blockIdx.x * blockDim.x + threadIdx.x;
    if (i < NN) g_counts[i] = 0;
    if (i == 0) g_offsets[NN] = EN;
}

// ---------------- hist ----------------
__global__ void hist_kernel(const int* __restrict__ edst) {
    int e = blockIdx.x * blockDim.x + threadIdx.x;
    if (e < EN) atomicAdd(&g_counts[edst[e]], 1);
}

// ---------------- scan: 3-kernel device-wide exclusive scan ----------------
#define SCAN_BLOCKS ((NN + 255) / 256)   // 196

__global__ __launch_bounds__(256) void scan_part() {
    int i = blockIdx.x * 256 + threadIdx.x;
    int c = (i < NN) ? g_counts[i] : 0;
    int v = c;
#pragma unroll
    for (int off = 16; off; off >>= 1) v += __shfl_down_sync(0xffffffffu, v, off);
    __shared__ int ws[8];
    if ((threadIdx.x & 31) == 0) ws[threadIdx.x >> 5] = v;
    __syncthreads();
    if (threadIdx.x == 0) {
        int s = 0;
#pragma unroll
        for (int j = 0; j < 8; j++) s += ws[j];
        g_bsum[blockIdx.x] = s;
    }
}

__global__ __launch_bounds__(256) void scan_mid() {
    __shared__ int ss[256];
    int tid = threadIdx.x;
    int v = (tid < SCAN_BLOCKS) ? g_bsum[tid] : 0;
    ss[tid] = v;
    __syncthreads();
#pragma unroll
    for (int off = 1; off < 256; off <<= 1) {
        int t = (tid >= off) ? ss[tid - off] : 0;
        __syncthreads();
        ss[tid] += t;
        __syncthreads();
    }
    if (tid < SCAN_BLOCKS) g_bsum[tid] = ss[tid] - v;   // exclusive
}

__global__ __launch_bounds__(256) void scan_final() {
    __shared__ int ss[256];
    int tid = threadIdx.x;
    int i = blockIdx.x * 256 + tid;
    int c = (i < NN) ? g_counts[i] : 0;
    ss[tid] = c;
    __syncthreads();
#pragma unroll
    for (int off = 1; off < 256; off <<= 1) {
        int t = (tid >= off) ? ss[tid - off] : 0;
        __syncthreads();
        ss[tid] += t;
        __syncthreads();
    }
    if (i < NN) {
        int excl = ss[tid] - c + g_bsum[blockIdx.x];
        g_offsets[i] = excl;
        g_cursor[i] = excl;
    }
}

// ---------------- fill: CSR slots + (src,dst) companion ----------------
__global__ void fill_kernel(const int* __restrict__ esrc, const int* __restrict__ edst) {
    int e = blockIdx.x * blockDim.x + threadIdx.x;
    if (e < EN) {
        int d = edst[e];
        int s = esrc[e];
        int p = atomicAdd(&g_cursor[d], 1);
        g_csr[p] = e;
        g_sd[p] = make_int2(s, d);
    }
}

// ---------------- node GEMM (HMMA, reg-prefetch pipeline) ----------------
#define NA_HI 0u
#define NA_LO 10240u
#define NB_HI 20480u
#define NB_LO 30720u
#define NODE_SMEM 40960

__global__ __launch_bounds__(256, 1) void node_gemm_tc(
    const float* __restrict__ x,
    const float* __restrict__ Wl, const float* __restrict__ bl,
    const float* __restrict__ Wr, const float* __restrict__ br,
    const float* __restrict__ Wres, const float* __restrict__ bres)
{
    extern __shared__ char smem[];
    uint32_t sb = s2u(smem);
    int tid = threadIdx.x, lane = tid & 31, wid = tid >> 5;
    int mwarp = wid >> 1, nwarp = wid & 1;
    int m0 = blockIdx.x * 128;
    int mat = blockIdx.y >> 1;
    int nhalf = blockIdx.y & 1;
    bool isBase = (mat == 2);

    const float* W  = (mat == 0) ? Wl : ((mat == 1) ? Wr : Wres);
    const float* bv = (mat == 0) ? bl : ((mat == 1) ? br : bres);
    uint32_t* outh  = (mat == 0) ? g_xlh : g_xrh;
    int ncol0 = nhalf * 128;

    int srow[4], skq[4];
    const float* aptr[4];
    const float* bptr[4];
#pragma unroll
    for (int it = 0; it < 4; it++) {
        int i = tid + it * 256;
        int r = i >> 3, kq = (i & 7) << 2;
        srow[it] = r; skq[it] = kq;
        int m = m0 + r; if (m >= NN) m = NN - 1;
        aptr[it] = x + (size_t)m * DD + kq;
        bptr[it] = W + (size_t)(ncol0 + r) * DD + kq;
    }

    float acc[2][8][4];
#pragma unroll
    for (int i = 0; i < 2; i++)
#pragma unroll
        for (int j = 0; j < 8; j++)
#pragma unroll
            for (int k = 0; k < 4; k++) acc[i][j][k] = 0.f;

    float4 ra[4], rb[4];
#pragma unroll
    for (int it = 0; it < 4; it++) {
        ra[it] = __ldg((const float4*)(aptr[it]));
        rb[it] = __ldg((const float4*)(bptr[it]));
    }

    for (int c = 0; c < 8; c++) {
        __syncthreads();
#pragma unroll
        for (int it = 0; it < 4; it++) {
            uint32_t off = (uint32_t)(srow[it] * 40 + skq[it]) * 2;
            *(uint2*)(smem + NA_HI + off) = pack4(ra[it], false);
            *(uint2*)(smem + NA_LO + off) = pack4(ra[it], true);
            *(uint2*)(smem + NB_HI + off) = pack4(rb[it], false);
            if (isBase)
                *(uint2*)(smem + NB_LO + off) = pack4(rb[it], true);
        }
        __syncthreads();
        if (c < 7) {
            int k0 = (c + 1) * 32;
#pragma unroll
            for (int it = 0; it < 4; it++) {
                ra[it] = __ldg((const float4*)(aptr[it] + k0));
                rb[it] = __ldg((const float4*)(bptr[it] + k0));
            }
        }
        mma_chunk1(acc, sb + NA_HI, sb + NB_HI, mwarp, nwarp, lane);
        mma_chunk1(acc, sb + NA_LO, sb + NB_HI, mwarp, nwarp, lane);
        if (isBase)
            mma_chunk1(acc, sb + NA_HI, sb + NB_LO, mwarp, nwarp, lane);
    }

#pragma unroll
    for (int mt = 0; mt < 2; mt++) {
        int row = m0 + mwarp * 32 + mt * 16 + (lane >> 2);
#pragma unroll
        for (int nt = 0; nt < 8; nt++) {
            int col = ncol0 + nwarp * 64 + nt * 8 + ((lane & 3) << 1);
            float b0 = __ldg(&bv[col]), b1 = __ldg(&bv[col + 1]);
            float v0 = acc[mt][nt][0] + b0, v1 = acc[mt][nt][1] + b1;
            float v2 = acc[mt][nt][2] + b0, v3 = acc[mt][nt][3] + b1;
            if (isBase) {
                if (row < NN) {
                    float2 v = {v0, v1};
                    *(float2*)(g_base + (size_t)row * DD + col) = v;
                }
                if (row + 8 < NN) {
                    float2 v = {v2, v3};
                    *(float2*)(g_base + (size_t)(row + 8) * DD + col) = v;
                }
            } else {
                if (row < NN)
                    outh[(size_t)row * 128 + (col >> 1)] = bfpack2(v0, v1);
                if (row + 8 < NN)
                    outh[(size_t)(row + 8) * 128 + (col >> 1)] = bfpack2(v2, v3);
            }
        }
    }
}

// ---------------- edge kernel: CSR-ordered; fused ee GEMM + logits, no atomics ----------
#define EE_OFF  0u                  // 128 x 133 u32 = 68096 B
#define EA_OFF  68096u              // 2 chunks x 128 x 40 bf16 = 20480 B
#define EB_OFF  (EA_OFF + 20480u)
#define EIDX    (EB_OFF + 20480u)   // sE(512) sSrc(512) sDst(512)
#define EDGE_SMEM (EIDX + 1536u)    // 110592 -> 2 CTAs/SM

__global__ __launch_bounds__(256, 2) void edge_kernel_tc(
    const float* __restrict__ ea,
    const float* __restrict__ We,
    const float* __restrict__ att)
{
    extern __shared__ char smem[];
    uint32_t sb = s2u(smem);
    int tid = threadIdx.x, lane = tid & 31, wid = tid >> 5;
    int mwarp = wid >> 1, nwarp = wid & 1;
    int p0 = blockIdx.x * 128;   // CSR slot base
    int* sE   = (int*)(smem + EIDX);
    int* sSrc = sE + 128;
    int* sDst = sSrc + 128;
    uint32_t* ee32 = (uint32_t*)(smem + EE_OFF);

    if (tid < 128) {
        sE[tid] = __ldg(&g_csr[p0 + tid]);
        int2 sd = __ldg(&g_sd[p0 + tid]);
        sSrc[tid] = sd.x;
        sDst[tid] = sd.y;
    }
    __syncthreads();

    // stage A: gathered edge_attr rows (CSR order), hi bf16
#pragma unroll
    for (int it = 0; it < 8; it++) {
        int i = tid + it * 256;
        int r = i >> 4, kq = (i & 15) << 2;
        int e = sE[r];
        float4 v = __ldg((const float4*)(ea + (size_t)e * DE + kq));
        int ch = kq >> 5, kc = kq & 31;
        uint32_t off = (uint32_t)(ch * 5120 + r * 40 + kc) * 2;
        *(uint2*)(smem + EA_OFF + off) = pack4(v, false);
    }

    for (int nh = 0; nh < 2; nh++) {
        if (nh) __syncthreads();
#pragma unroll
        for (int it = 0; it < 8; it++) {
            int i = tid + it * 256;
            int r = i >> 4, kq = (i & 15) << 2;
            float4 v = __ldg((const float4*)(We + (size_t)(nh * 128 + r) * DE + kq));
            int ch = kq >> 5, kc = kq & 31;
            uint32_t off = (uint32_t)(ch * 5120 + r * 40 + kc) * 2;
            *(uint2*)(smem + EB_OFF + off) = pack4(v, false);
        }
        __syncthreads();

        float acc[2][8][4];
#pragma unroll
        for (int i = 0; i < 2; i++)
#pragma unroll
            for (int j = 0; j < 8; j++)
#pragma unroll
                for (int k = 0; k < 4; k++) acc[i][j][k] = 0.f;

#pragma unroll
        for (int c = 0; c < 2; c++)
            mma_chunk1(acc, sb + EA_OFF + c * 10240, sb + EB_OFF + c * 10240,
                       mwarp, nwarp, lane);

#pragma unroll
        for (int mt = 0; mt < 2; mt++) {
            int el = mwarp * 32 + mt * 16 + (lane >> 2);
#pragma unroll
            for (int nt = 0; nt < 8; nt++) {
                int w = nh * 64 + nwarp * 32 + nt * 4 + (lane & 3);
                ee32[el * 133 + w]       = bfpack2(acc[mt][nt][0], acc[mt][nt][1]);
                ee32[(el + 8) * 133 + w] = bfpack2(acc[mt][nt][2], acc[mt][nt][3]);
            }
        }
    }
    __syncthreads();

    // logit phase: quad per edge; xr rows repeat across dst-runs -> L1 hits
    int q = tid & 3;
    for (int rep = 0; rep < 2; rep++) {
        int el = (tid >> 2) + rep * 64;
        int s = sSrc[el];
        int d = sDst[el];
        const uint32_t* xlp = g_xlh + (size_t)s * 128;
        const uint32_t* xrp = g_xrh + (size_t)d * 128;
        uint32_t eeb = el * 133 + q * 4;
#pragma unroll
        for (int h = 0; h < 8; h++) {
            int cb  = h * 32 + q * 8;
            int cb2 = h * 16 + q * 4;
            uint4 U = __ldg((const uint4*)(xlp + cb2));
            uint4 R = __ldg((const uint4*)(xrp + cb2));
            float2 u0 = unpk(U.x), u1 = unpk(U.y), u2 = unpk(U.z), u3 = unpk(U.w);
            float2 r0 = unpk(R.x), r1 = unpk(R.y), r2 = unpk(R.z), r3 = unpk(R.w);
            float2 f0 = unpk(ee32[eeb + h * 16 + 0]);
            float2 f1 = unpk(ee32[eeb + h * 16 + 1]);
            float2 f2 = unpk(ee32[eeb + h * 16 + 2]);
            float2 f3 = unpk(ee32[eeb + h * 16 + 3]);
            float4 a0 = __ldg((const float4*)(att + cb));
            float4 a1 = __ldg((const float4*)(att + cb + 4));
            float p = 0.f, z;
            z = u0.x + r0.x + f0.x; z = (z > 0.f) ? z : NEG * z; p += z * a0.x;
            z = u0.y + r0.y + f0.y; z = (z > 0.f) ? z : NEG * z; p += z * a0.y;
            z = u1.x + r1.x + f1.x; z = (z > 0.f) ? z : NEG * z; p += z * a0.z;
            z = u1.y + r1.y + f1.y; z = (z > 0.f) ? z : NEG * z; p += z * a0.w;
            z = u2.x + r2.x + f2.x; z = (z > 0.f) ? z : NEG * z; p += z * a1.x;
            z = u2.y + r2.y + f2.y; z = (z > 0.f) ? z : NEG * z; p += z * a1.y;
            z = u3.x + r3.x + f3.x; z = (z > 0.f) ? z : NEG * z; p += z * a1.z;
            z = u3.y + r3.y + f3.y; z = (z > 0.f) ? z : NEG * z; p += z * a1.w;
            p += __shfl_xor_sync(0xffffffffu, p, 1);
            p += __shfl_xor_sync(0xffffffffu, p, 2);
            if (q == 0)
                g_w[(size_t)(p0 + el) * HH + h] = __expf(p);
        }
    }
}

// ---------------- aggregation + residual + LayerNorm (warp-per-node, fully streamed) ---
__device__ __forceinline__ void addw(float* acc, uint4 X, float w) {
    float2 f0 = unpk(X.x), f1 = unpk(X.y), f2 = unpk(X.z), f3 = unpk(X.w);
    acc[0] += f0.x * w; acc[1] += f0.y * w;
    acc[2] += f1.x * w; acc[3] += f1.y * w;
    acc[4] += f2.x * w; acc[5] += f2.y * w;
    acc[6] += f3.x * w; acc[7] += f3.y * w;
}

__global__ __launch_bounds__(256) void aggregate_ln_kernel(
    const float* __restrict__ gamma,
    const float* __restrict__ beta,
    float* __restrict__ out)
{
    int lane = threadIdx.x & 31;
    int i = blockIdx.x * 8 + (threadIdx.x >> 5);
    if (i >= NN) return;
    int h = lane >> 2;                 // head of this lane's 8 channels
    int p0 = g_offsets[i], p1 = g_offsets[i + 1];

    float acc[8];
#pragma unroll
    for (int k = 0; k < 8; k++) acc[k] = 0.f;
    float wsum = 0.f;

    for (int b0 = p0; b0 < p1; b0 += 32) {
        int n = min(32, p1 - b0);
        int s = 0;
        if (lane < n) s = __ldg(&g_sd[b0 + lane]).x;
        int j = 0;
        for (; j + 4 <= n; j += 4) {
            int s0 = __shfl_sync(0xffffffffu, s, j + 0);
            int s1 = __shfl_sync(0xffffffffu, s, j + 1);
            int s2 = __shfl_sync(0xffffffffu, s, j + 2);
            int s3 = __shfl_sync(0xffffffffu, s, j + 3);
            float w0 = __ldg(&g_w[(size_t)(b0 + j + 0) * HH + h]);
            float w1 = __ldg(&g_w[(size_t)(b0 + j + 1) * HH + h]);
            float w2 = __ldg(&g_w[(size_t)(b0 + j + 2) * HH + h]);
            float w3 = __ldg(&g_w[(size_t)(b0 + j + 3) * HH + h]);
            uint4 X0 = __ldg((const uint4*)(g_xlh + (size_t)s0 * 128) + lane);
            uint4 X1 = __ldg((const uint4*)(g_xlh + (size_t)s1 * 128) + lane);
            uint4 X2 = __ldg((const uint4*)(g_xlh + (size_t)s2 * 128) + lane);
            uint4 X3 = __ldg((const uint4*)(g_xlh + (size_t)s3 * 128) + lane);
            addw(acc, X0, w0);
            addw(acc, X1, w1);
            addw(acc, X2, w2);
            addw(acc, X3, w3);
            wsum += w0 + w1 + w2 + w3;
        }
        for (; j < n; j++) {
            int sj = __shfl_sync(0xffffffffu, s, j);
            float wj = __ldg(&g_w[(size_t)(b0 + j) * HH + h]);
            uint4 X = __ldg((const uint4*)(g_xlh + (size_t)sj * 128) + lane);
            addw(acc, X, wj);
            wsum += wj;
        }
    }

    float invd = (wsum > 0.f) ? (1.f / wsum) : 0.f;
    const float* bp = g_base + (size_t)i * DD + lane * 8;
    float4 bb0 = __ldg((const float4*)bp);
    float4 bb1 = __ldg((const float4*)(bp + 4));
    float v[8];
    v[0] = acc[0] * invd + bb0.x; v[1] = acc[1] * invd + bb0.y;
    v[2] = acc[2] * invd + bb0.z; v[3] = acc[3] * invd + bb0.w;
    v[4] = acc[4] * invd + bb1.x; v[5] = acc[5] * invd + bb1.y;
    v[6] = acc[6] * invd + bb1.z; v[7] = acc[7] * invd + bb1.w;

    float s1 = 0.f, s2 = 0.f;
#pragma unroll
    for (int k = 0; k < 8; k++) { s1 += v[k]; s2 += v[k] * v[k]; }
#pragma unroll
    for (int off = 16; off; off >>= 1) {
        s1 += __shfl_xor_sync(0xffffffffu, s1, off);
        s2 += __shfl_xor_sync(0xffffffffu, s2, off);
    }
    float mu = s1 * (1.f / DD);
    float var = s2 * (1.f / DD) - mu * mu;
    float rstd = rsqrtf(fmaxf(var, 0.f) + 1e-5f);

    const float* gp = gamma + lane * 8;
    const float* btp = beta + lane * 8;
    float4 g0 = __ldg((const float4*)gp), g1 = __ldg((const float4*)(gp + 4));
    float4 t0 = __ldg((const float4*)btp), t1 = __ldg((const float4*)(btp + 4));
    float* op = out + (size_t)i * DD + lane * 8;
    float4 o0, o1;
    o0.x = (v[0] - mu) * rstd * g0.x + t0.x;
    o0.y = (v[1] - mu) * rstd * g0.y + t0.y;
    o0.z = (v[2] - mu) * rstd * g0.z + t0.z;
    o0.w = (v[3] - mu) * rstd * g0.w + t0.w;
    o1.x = (v[4] - mu) * rstd * g1.x + t1.x;
    o1.y = (v[5] - mu) * rstd * g1.y + t1.y;
    o1.z = (v[6] - mu) * rstd * g1.z + t1.z;
    o1.w = (v[7] - mu) * rstd * g1.w + t1.w;
    *(float4*)op = o0;
    *(float4*)(op + 4) = o1;
}

// ---------------- launch ----------------
extern "C" void kernel_launch(void* const* d_in, const int* in_sizes, int n_in,
                              void* d_out, int out_size)
{
    const float *x, *ea, *Wl, *bl, *Wr, *br, *We, *att, *Wres, *bias, *gamma, *beta;
    const int* eidx;

    if (n_in >= 13 && in_sizes[2] == 2 * EN) {
        x     = (const float*)d_in[0];
        ea    = (const float*)d_in[1];
        eidx  = (const int*)  d_in[2];
        Wl    = (const float*)d_in[3];
        bl    = (const float*)d_in[4];
        Wr    = (const float*)d_in[5];
        br    = (const float*)d_in[6];
        We    = (const float*)d_in[7];
        att   = (const float*)d_in[8];
        Wres  = (const float*)d_in[9];
        bias  = (const float*)d_in[10];
        gamma = (const float*)d_in[11];
        beta  = (const float*)d_in[12];
    } else {
        x     = (const float*)d_in[0];
        ea    = (const float*)d_in[1];
        Wl    = (const float*)d_in[2];
        bl    = (const float*)d_in[3];
        Wr    = (const float*)d_in[4];
        br    = (const float*)d_in[5];
        We    = (const float*)d_in[6];
        att   = (const float*)d_in[7];
        Wres  = (const float*)d_in[8];
        bias  = (const float*)d_in[9];
        gamma = (const float*)d_in[10];
        beta  = (const float*)d_in[11];
        eidx  = (const int*)  d_in[12];
    }
    const int* esrc = eidx;
    const int* edst = eidx + EN;
    float* out = (float*)d_out;

    cudaFuncSetAttribute(node_gemm_tc, cudaFuncAttributeMaxDynamicSharedMemorySize, NODE_SMEM);
    cudaFuncSetAttribute(edge_kernel_tc, cudaFuncAttributeMaxDynamicSharedMemorySize, EDGE_SMEM);

    zero_kernel<<<(NN + 255) / 256, 256>>>();
    hist_kernel<<<(EN + 255) / 256, 256>>>(edst);
    scan_part<<<SCAN_BLOCKS, 256>>>();
    scan_mid<<<1, 256>>>();
    scan_final<<<SCAN_BLOCKS, 256>>>();
    fill_kernel<<<(EN + 255) / 256, 256>>>(esrc, edst);
    node_gemm_tc<<<dim3((NN + 127) / 128, 6), 256, NODE_SMEM>>>(x, Wl, bl, Wr, br, Wres, bias);
    edge_kernel_tc<<<EN / 128, 256, EDGE_SMEM>>>(ea, We, att);
    aggregate_ln_kernel<<<(NN + 7) / 8, 256>>>(gamma, beta, out);
}

// round 17
// speedup vs baseline: 4.7405x; 1.0302x over previous
#include <cuda_runtime.h>
#include <cuda_bf16.h>
#include <cstdint>

#define NN   50000
#define EN   800000
#define DD   256
#define HH   8
#define DE   64
#define NEG  0.2f

// ---------------- device scratch ----------------
__device__ float    g_base[(size_t)NN * DD];
__device__ uint32_t g_xlh[(size_t)NN * (DD / 2)];   // bf16x2 xl
__device__ uint32_t g_xrh[(size_t)NN * (DD / 2)];   // bf16x2 xr
__device__ float    g_w[(size_t)EN * HH];           // CSR-ordered softmax numerators
__device__ int      g_counts[NN];
__device__ int      g_offsets[NN + 1];
__device__ int      g_cursor[NN];
__device__ int      g_csr[EN];                      // CSR slot -> edge id
__device__ int2     g_sd[EN];                       // CSR slot -> (src, dst)
__device__ int      g_bsum[256];
__device__ uint32_t g_wepk[2 * 2 * 128 * 20];       // pre-packed We bf16 smem image

// ---------------- helpers ----------------
__device__ __forceinline__ uint32_t s2u(const void* p) {
    uint32_t a;
    asm("{ .reg .u64 t; cvta.to.shared.u64 t, %1; cvt.u32.u64 %0, t; }" : "=r"(a) : "l"(p));
    return a;
}
__device__ __forceinline__ void ldsm_x4(uint32_t* r, uint32_t addr) {
    asm volatile("ldmatrix.sync.aligned.m8n8.x4.shared.b16 {%0,%1,%2,%3}, [%4];"
        : "=r"(r[0]), "=r"(r[1]), "=r"(r[2]), "=r"(r[3]) : "r"(addr));
}
__device__ __forceinline__ void mma16816(float* c, const uint32_t* a, uint32_t b0, uint32_t b1) {
    asm volatile("mma.sync.aligned.m16n8k16.row.col.f32.bf16.bf16.f32 "
        "{%0,%1,%2,%3}, {%4,%5,%6,%7}, {%8,%9}, {%0,%1,%2,%3};"
        : "+f"(c[0]), "+f"(c[1]), "+f"(c[2]), "+f"(c[3])
        : "r"(a[0]), "r"(a[1]), "r"(a[2]), "r"(a[3]), "r"(b0), "r"(b1));
}
__device__ __forceinline__ uint2 pack4(float4 v, bool lo) {
    __nv_bfloat16 h0 = __float2bfloat16(v.x), h1 = __float2bfloat16(v.y);
    __nv_bfloat16 h2 = __float2bfloat16(v.z), h3 = __float2bfloat16(v.w);
    if (lo) {
        h0 = __float2bfloat16(v.x - __bfloat162float(h0));
        h1 = __float2bfloat16(v.y - __bfloat162float(h1));
        h2 = __float2bfloat16(v.z - __bfloat162float(h2));
        h3 = __float2bfloat16(v.w - __bfloat162float(h3));
    }
    uint2 r;
    r.x = ((uint32_t)__bfloat16_as_ushort(h1) << 16) | __bfloat16_as_ushort(h0);
    r.y = ((uint32_t)__bfloat16_as_ushort(h3) << 16) | __bfloat16_as_ushort(h2);
    return r;
}
__device__ __forceinline__ uint32_t bfpack2(float a, float b) {
    __nv_bfloat162 h;
    h.x = __float2bfloat16(a);
    h.y = __float2bfloat16(b);
    return *(uint32_t*)&h;
}
__device__ __forceinline__ float2 unpk(uint32_t u) {
    __nv_bfloat162 h = *(__nv_bfloat162*)&u;
    return __bfloat1622float2(h);
}

// fragment address helpers (pitch 40 bf16 per row)
__device__ __forceinline__ uint32_t a_frag_addr(uint32_t base, int mrow0, int kk, int lane) {
    int row = mrow0 + (lane & 15);
    int col = kk + ((lane >> 4) << 3);
    return base + (uint32_t)(row * 40 + col) * 2;
}
__device__ __forceinline__ uint32_t b_frag_addr(uint32_t base, int n0, int kk, int lane) {
    int row = n0 + (lane & 7) + ((lane >> 4) << 3);
    int col = kk + (((lane >> 3) & 1) << 3);
    return base + (uint32_t)(row * 40 + col) * 2;
}

__device__ __forceinline__ void mma_chunk1(
    float acc[2][8][4], uint32_t ab, uint32_t bb, int mwarp, int nwarp, int lane)
{
#pragma unroll
    for (int ks = 0; ks < 32; ks += 16) {
        uint32_t af[2][4];
        ldsm_x4(af[0], a_frag_addr(ab, mwarp * 32, ks, lane));
        ldsm_x4(af[1], a_frag_addr(ab, mwarp * 32 + 16, ks, lane));
#pragma unroll
        for (int ng = 0; ng < 4; ng++) {
            uint32_t bf[4];
            ldsm_x4(bf, b_frag_addr(bb, nwarp * 64 + ng * 16, ks, lane));
            mma16816(acc[0][2 * ng + 0], af[0], bf[0], bf[1]);
            mma16816(acc[0][2 * ng + 1], af[0], bf[2], bf[3]);
            mma16816(acc[1][2 * ng + 0], af[1], bf[0], bf[1]);
            mma16816(acc[1][2 * ng + 1], af[1], bf[2], bf[3]);
        }
    }
}

// ---------------- We pre-pack ----------------
__global__ __launch_bounds__(256) void pack_we_kernel(const float* __restrict__ We) {
    int i = blockIdx.x * 256 + threadIdx.x;   // 0..8191
    if (i >= 8192) return;
    int k2 = i & 15;
    int r  = (i >> 4) & 127;
    int ch = (i >> 11) & 1;
    int nh = (i >> 12) & 1;
    const float* p = We + (size_t)(nh * 128 + r) * DE + ch * 32 + k2 * 2;
    g_wepk[(size_t)((nh * 2 + ch) * 128 + r) * 20 + k2] = bfpack2(p[0], p[1]);
}

// ---------------- K0: zero counts ----------------
__global__ void zero_kernel() {
    int i = blockIdx.x * blockDim.x + threadIdx.x;
    if (i < NN) g_counts[i] = 0;
    if (i == 0) g_offsets[NN] = EN;
}

// ---------------- hist ----------------
__global__ void hist_kernel(const int* __restrict__ edst) {
    int e = blockIdx.x * blockDim.x + threadIdx.x;
    if (e < EN) atomicAdd(&g_counts[edst[e]], 1);
}

// ---------------- scan: 3-kernel device-wide exclusive scan ----------------
#define SCAN_BLOCKS ((NN + 255) / 256)   // 196

__global__ __launch_bounds__(256) void scan_part() {
    int i = blockIdx.x * 256 + threadIdx.x;
    int c = (i < NN) ? g_counts[i] : 0;
    int v = c;
#pragma unroll
    for (int off = 16; off; off >>= 1) v += __shfl_down_sync(0xffffffffu, v, off);
    __shared__ int ws[8];
    if ((threadIdx.x & 31) == 0) ws[threadIdx.x >> 5] = v;
    __syncthreads();
    if (threadIdx.x == 0) {
        int s = 0;
#pragma unroll
        for (int j = 0; j < 8; j++) s += ws[j];
        g_bsum[blockIdx.x] = s;
    }
}

__global__ __launch_bounds__(256) void scan_mid() {
    __shared__ int ss[256];
    int tid = threadIdx.x;
    int v = (tid < SCAN_BLOCKS) ? g_bsum[tid] : 0;
    ss[tid] = v;
    __syncthreads();
#pragma unroll
    for (int off = 1; off < 256; off <<= 1) {
        int t = (tid >= off) ? ss[tid - off] : 0;
        __syncthreads();
        ss[tid] += t;
        __syncthreads();
    }
    if (tid < SCAN_BLOCKS) g_bsum[tid] = ss[tid] - v;   // exclusive
}

__global__ __launch_bounds__(256) void scan_final() {
    __shared__ int ss[256];
    int tid = threadIdx.x;
    int i = blockIdx.x * 256 + tid;
    int c = (i < NN) ? g_counts[i] : 0;
    ss[tid] = c;
    __syncthreads();
#pragma unroll
    for (int off = 1; off < 256; off <<= 1) {
        int t = (tid >= off) ? ss[tid - off] : 0;
        __syncthreads();
        ss[tid] += t;
        __syncthreads();
    }
    if (i < NN) {
        int excl = ss[tid] - c + g_bsum[blockIdx.x];
        g_offsets[i] = excl;
        g_cursor[i] = excl;
    }
}

// ---------------- fill: CSR slots + (src,dst) companion ----------------
__global__ void fill_kernel(const int* __restrict__ esrc, const int* __restrict__ edst) {
    int e = blockIdx.x * blockDim.x + threadIdx.x;
    if (e < EN) {
        int d = edst[e];
        int s = esrc[e];
        int p = atomicAdd(&g_cursor[d], 1);
        g_csr[p] = e;
        g_sd[p] = make_int2(s, d);
    }
}

// ---------------- node GEMM (HMMA, reg-prefetch pipeline) ----------------
#define NA_HI 0u
#define NA_LO 10240u
#define NB_HI 20480u
#define NB_LO 30720u
#define NODE_SMEM 40960

__global__ __launch_bounds__(256, 1) void node_gemm_tc(
    const float* __restrict__ x,
    const float* __restrict__ Wl, const float* __restrict__ bl,
    const float* __restrict__ Wr, const float* __restrict__ br,
    const float* __restrict__ Wres, const float* __restrict__ bres)
{
    extern __shared__ char smem[];
    uint32_t sb = s2u(smem);
    int tid = threadIdx.x, lane = tid & 31, wid = tid >> 5;
    int mwarp = wid >> 1, nwarp = wid & 1;
    int m0 = blockIdx.x * 128;
    int mat = blockIdx.y >> 1;
    int nhalf = blockIdx.y & 1;
    bool isBase = (mat == 2);

    const float* W  = (mat == 0) ? Wl : ((mat == 1) ? Wr : Wres);
    const float* bv = (mat == 0) ? bl : ((mat == 1) ? br : bres);
    uint32_t* outh  = (mat == 0) ? g_xlh : g_xrh;
    int ncol0 = nhalf * 128;

    int srow[4], skq[4];
    const float* aptr[4];
    const float* bptr[4];
#pragma unroll
    for (int it = 0; it < 4; it++) {
        int i = tid + it * 256;
        int r = i >> 3, kq = (i & 7) << 2;
        srow[it] = r; skq[it] = kq;
        int m = m0 + r; if (m >= NN) m = NN - 1;
        aptr[it] = x + (size_t)m * DD + kq;
        bptr[it] = W + (size_t)(ncol0 + r) * DD + kq;
    }

    float acc[2][8][4];
#pragma unroll
    for (int i = 0; i < 2; i++)
#pragma unroll
        for (int j = 0; j < 8; j++)
#pragma unroll
            for (int k = 0; k < 4; k++) acc[i][j][k] = 0.f;

    float4 ra[4], rb[4];
#pragma unroll
    for (int it = 0; it < 4; it++) {
        ra[it] = __ldg((const float4*)(aptr[it]));
        rb[it] = __ldg((const float4*)(bptr[it]));
    }

    for (int c = 0; c < 8; c++) {
        __syncthreads();
#pragma unroll
        for (int it = 0; it < 4; it++) {
            uint32_t off = (uint32_t)(srow[it] * 40 + skq[it]) * 2;
            *(uint2*)(smem + NA_HI + off) = pack4(ra[it], false);
            *(uint2*)(smem + NA_LO + off) = pack4(ra[it], true);
            *(uint2*)(smem + NB_HI + off) = pack4(rb[it], false);
            if (isBase)
                *(uint2*)(smem + NB_LO + off) = pack4(rb[it], true);
        }
        __syncthreads();
        if (c < 7) {
            int k0 = (c + 1) * 32;
#pragma unroll
            for (int it = 0; it < 4; it++) {
                ra[it] = __ldg((const float4*)(aptr[it] + k0));
                rb[it] = __ldg((const float4*)(bptr[it] + k0));
            }
        }
        mma_chunk1(acc, sb + NA_HI, sb + NB_HI, mwarp, nwarp, lane);
        mma_chunk1(acc, sb + NA_LO, sb + NB_HI, mwarp, nwarp, lane);
        if (isBase)
            mma_chunk1(acc, sb + NA_HI, sb + NB_LO, mwarp, nwarp, lane);
    }

#pragma unroll
    for (int mt = 0; mt < 2; mt++) {
        int row = m0 + mwarp * 32 + mt * 16 + (lane >> 2);
#pragma unroll
        for (int nt = 0; nt < 8; nt++) {
            int col = ncol0 + nwarp * 64 + nt * 8 + ((lane & 3) << 1);
            float b0 = __ldg(&bv[col]), b1 = __ldg(&bv[col + 1]);
            float v0 = acc[mt][nt][0] + b0, v1 = acc[mt][nt][1] + b1;
            float v2 = acc[mt][nt][2] + b0, v3 = acc[mt][nt][3] + b1;
            if (isBase) {
                if (row < NN) {
                    float2 v = {v0, v1};
                    *(float2*)(g_base + (size_t)row * DD + col) = v;
                }
                if (row + 8 < NN) {
                    float2 v = {v2, v3};
                    *(float2*)(g_base + (size_t)(row + 8) * DD + col) = v;
                }
            } else {
                if (row < NN)
                    outh[(size_t)row * 128 + (col >> 1)] = bfpack2(v0, v1);
                if (row + 8 < NN)
                    outh[(size_t)(row + 8) * 128 + (col >> 1)] = bfpack2(v2, v3);
            }
        }
    }
}

// ---------------- edge kernel: CSR-ordered; fused ee GEMM + logits, no atomics ----------
#define EE_OFF  0u                  // 128 x 133 u32 = 68096 B
#define EA_OFF  68096u              // 2 chunks x 128 x 40 bf16 = 20480 B
#define EB_OFF  (EA_OFF + 20480u)
#define EIDX    (EB_OFF + 20480u)   // sE(512) sSrc(512) sDst(512)
#define EDGE_SMEM (EIDX + 1536u)    // 110592 -> 2 CTAs/SM

__global__ __launch_bounds__(256, 2) void edge_kernel_tc(
    const float* __restrict__ ea,
    const float* __restrict__ att)
{
    extern __shared__ char smem[];
    uint32_t sb = s2u(smem);
    int tid = threadIdx.x, lane = tid & 31, wid = tid >> 5;
    int mwarp = wid >> 1, nwarp = wid & 1;
    int p0 = blockIdx.x * 128;   // CSR slot base
    int* sE   = (int*)(smem + EIDX);
    int* sSrc = sE + 128;
    int* sDst = sSrc + 128;
    uint32_t* ee32 = (uint32_t*)(smem + EE_OFF);

    if (tid < 128) {
        sE[tid] = __ldg(&g_csr[p0 + tid]);
        int2 sd = __ldg(&g_sd[p0 + tid]);
        sSrc[tid] = sd.x;
        sDst[tid] = sd.y;
    }
    __syncthreads();

    // stage A: gathered edge_attr rows (CSR order), hi bf16
#pragma unroll
    for (int it = 0; it < 8; it++) {
        int i = tid + it * 256;
        int r = i >> 4, kq = (i & 15) << 2;
        int e = sE[r];
        float4 v = __ldg((const float4*)(ea + (size_t)e * DE + kq));
        int ch = kq >> 5, kc = kq & 31;
        uint32_t off = (uint32_t)(ch * 5120 + r * 40 + kc) * 2;
        *(uint2*)(smem + EA_OFF + off) = pack4(v, false);
    }

    for (int nh = 0; nh < 2; nh++) {
        if (nh) __syncthreads();
        // stage B: contiguous copy of pre-packed We image
        {
            const uint4* srcp = (const uint4*)(g_wepk + (size_t)nh * 2 * 128 * 20);
            uint4* dstp = (uint4*)(smem + EB_OFF);
#pragma unroll
            for (int i = tid; i < 1280; i += 256)
                dstp[i] = __ldg(srcp + i);
        }
        __syncthreads();

        float acc[2][8][4];
#pragma unroll
        for (int i = 0; i < 2; i++)
#pragma unroll
            for (int j = 0; j < 8; j++)
#pragma unroll
                for (int k = 0; k < 4; k++) acc[i][j][k] = 0.f;

#pragma unroll
        for (int c = 0; c < 2; c++)
            mma_chunk1(acc, sb + EA_OFF + c * 10240, sb + EB_OFF + c * 10240,
                       mwarp, nwarp, lane);

#pragma unroll
        for (int mt = 0; mt < 2; mt++) {
            int el = mwarp * 32 + mt * 16 + (lane >> 2);
#pragma unroll
            for (int nt = 0; nt < 8; nt++) {
                int w = nh * 64 + nwarp * 32 + nt * 4 + (lane & 3);
                ee32[el * 133 + w]       = bfpack2(acc[mt][nt][0], acc[mt][nt][1]);
                ee32[(el + 8) * 133 + w] = bfpack2(acc[mt][nt][2], acc[mt][nt][3]);
            }
        }
    }
    __syncthreads();

    // logit phase: quad per edge; xr rows repeat across dst-runs -> L1 hits
    int q = tid & 3;
    for (int rep = 0; rep < 2; rep++) {
        int el = (tid >> 2) + rep * 64;
        int s = sSrc[el];
        int d = sDst[el];
        const uint32_t* xlp = g_xlh + (size_t)s * 128;
        const uint32_t* xrp = g_xrh + (size_t)d * 128;
        uint32_t eeb = el * 133 + q * 4;
#pragma unroll
        for (int h = 0; h < 8; h++) {
            int cb  = h * 32 + q * 8;
            int cb2 = h * 16 + q * 4;
            uint4 U = __ldg((const uint4*)(xlp + cb2));
            uint4 R = __ldg((const uint4*)(xrp + cb2));
            float2 u0 = unpk(U.x), u1 = unpk(U.y), u2 = unpk(U.z), u3 = unpk(U.w);
            float2 r0 = unpk(R.x), r1 = unpk(R.y), r2 = unpk(R.z), r3 = unpk(R.w);
            float2 f0 = unpk(ee32[eeb + h * 16 + 0]);
            float2 f1 = unpk(ee32[eeb + h * 16 + 1]);
            float2 f2 = unpk(ee32[eeb + h * 16 + 2]);
            float2 f3 = unpk(ee32[eeb + h * 16 + 3]);
            float4 a0 = __ldg((const float4*)(att + cb));
            float4 a1 = __ldg((const float4*)(att + cb + 4));
            float p = 0.f, z;
            z = u0.x + r0.x + f0.x; z = (z > 0.f) ? z : NEG * z; p += z * a0.x;
            z = u0.y + r0.y + f0.y; z = (z > 0.f) ? z : NEG * z; p += z * a0.y;
            z = u1.x + r1.x + f1.x; z = (z > 0.f) ? z : NEG * z; p += z * a0.z;
            z = u1.y + r1.y + f1.y; z = (z > 0.f) ? z : NEG * z; p += z * a0.w;
            z = u2.x + r2.x + f2.x; z = (z > 0.f) ? z : NEG * z; p += z * a1.x;
            z = u2.y + r2.y + f2.y; z = (z > 0.f) ? z : NEG * z; p += z * a1.y;
            z = u3.x + r3.x + f3.x; z = (z > 0.f) ? z : NEG * z; p += z * a1.z;
            z = u3.y + r3.y + f3.y; z = (z > 0.f) ? z : NEG * z; p += z * a1.w;
            p += __shfl_xor_sync(0xffffffffu, p, 1);
            p += __shfl_xor_sync(0xffffffffu, p, 2);
            if (q == 0)
                g_w[(size_t)(p0 + el) * HH + h] = __expf(p);
        }
    }
}

// ---------------- aggregation + residual + LayerNorm (warp-per-node, fully streamed) ---
__device__ __forceinline__ void addw(float* acc, uint4 X, float w) {
    float2 f0 = unpk(X.x), f1 = unpk(X.y), f2 = unpk(X.z), f3 = unpk(X.w);
    acc[0] += f0.x * w; acc[1] += f0.y * w;
    acc[2] += f1.x * w; acc[3] += f1.y * w;
    acc[4] += f2.x * w; acc[5] += f2.y * w;
    acc[6] += f3.x * w; acc[7] += f3.y * w;
}

__global__ __launch_bounds__(256) void aggregate_ln_kernel(
    const float* __restrict__ gamma,
    const float* __restrict__ beta,
    float* __restrict__ out)
{
    int lane = threadIdx.x & 31;
    int i = blockIdx.x * 8 + (threadIdx.x >> 5);
    if (i >= NN) return;
    int h = lane >> 2;                 // head of this lane's 8 channels
    int p0 = g_offsets[i], p1 = g_offsets[i + 1];

    float acc[8];
#pragma unroll
    for (int k = 0; k < 8; k++) acc[k] = 0.f;
    float wsum = 0.f;

    for (int b0 = p0; b0 < p1; b0 += 32) {
        int n = min(32, p1 - b0);
        int s = 0;
        if (lane < n) s = __ldg(&g_sd[b0 + lane]).x;
        int j = 0;
        for (; j + 4 <= n; j += 4) {
            int s0 = __shfl_sync(0xffffffffu, s, j + 0);
            int s1 = __shfl_sync(0xffffffffu, s, j + 1);
            int s2 = __shfl_sync(0xffffffffu, s, j + 2);
            int s3 = __shfl_sync(0xffffffffu, s, j + 3);
            float w0 = __ldg(&g_w[(size_t)(b0 + j + 0) * HH + h]);
            float w1 = __ldg(&g_w[(size_t)(b0 + j + 1) * HH + h]);
            float w2 = __ldg(&g_w[(size_t)(b0 + j + 2) * HH + h]);
            float w3 = __ldg(&g_w[(size_t)(b0 + j + 3) * HH + h]);
            uint4 X0 = __ldg((const uint4*)(g_xlh + (size_t)s0 * 128) + lane);
            uint4 X1 = __ldg((const uint4*)(g_xlh + (size_t)s1 * 128) + lane);
            uint4 X2 = __ldg((const uint4*)(g_xlh + (size_t)s2 * 128) + lane);
            uint4 X3 = __ldg((const uint4*)(g_xlh + (size_t)s3 * 128) + lane);
            addw(acc, X0, w0);
            addw(acc, X1, w1);
            addw(acc, X2, w2);
            addw(acc, X3, w3);
            wsum += w0 + w1 + w2 + w3;
        }
        for (; j < n; j++) {
            int sj = __shfl_sync(0xffffffffu, s, j);
            float wj = __ldg(&g_w[(size_t)(b0 + j) * HH + h]);
            uint4 X = __ldg((const uint4*)(g_xlh + (size_t)sj * 128) + lane);
            addw(acc, X, wj);
            wsum += wj;
        }
    }

    float invd = (wsum > 0.f) ? (1.f / wsum) : 0.f;
    const float* bp = g_base + (size_t)i * DD + lane * 8;
    float4 bb0 = __ldg((const float4*)bp);
    float4 bb1 = __ldg((const float4*)(bp + 4));
    float v[8];
    v[0] = acc[0] * invd + bb0.x; v[1] = acc[1] * invd + bb0.y;
    v[2] = acc[2] * invd + bb0.z; v[3] = acc[3] * invd + bb0.w;
    v[4] = acc[4] * invd + bb1.x; v[5] = acc[5] * invd + bb1.y;
    v[6] = acc[6] * invd + bb1.z; v[7] = acc[7] * invd + bb1.w;

    float s1 = 0.f, s2 = 0.f;
#pragma unroll
    for (int k = 0; k < 8; k++) { s1 += v[k]; s2 += v[k] * v[k]; }
#pragma unroll
    for (int off = 16; off; off >>= 1) {
        s1 += __shfl_xor_sync(0xffffffffu, s1, off);
        s2 += __shfl_xor_sync(0xffffffffu, s2, off);
    }
    float mu = s1 * (1.f / DD);
    float var = s2 * (1.f / DD) - mu * mu;
    float rstd = rsqrtf(fmaxf(var, 0.f) + 1e-5f);

    const float* gp = gamma + lane * 8;
    const float* btp = beta + lane * 8;
    float4 g0 = __ldg((const float4*)gp), g1 = __ldg((const float4*)(gp + 4));
    float4 t0 = __ldg((const float4*)btp), t1 = __ldg((const float4*)(btp + 4));
    float* op = out + (size_t)i * DD + lane * 8;
    float4 o0, o1;
    o0.x = (v[0] - mu) * rstd * g0.x + t0.x;
    o0.y = (v[1] - mu) * rstd * g0.y + t0.y;
    o0.z = (v[2] - mu) * rstd * g0.z + t0.z;
    o0.w = (v[3] - mu) * rstd * g0.w + t0.w;
    o1.x = (v[4] - mu) * rstd * g1.x + t1.x;
    o1.y = (v[5] - mu) * rstd * g1.y + t1.y;
    o1.z = (v[6] - mu) * rstd * g1.z + t1.z;
    o1.w = (v[7] - mu) * rstd * g1.w + t1.w;
    *(float4*)op = o0;
    *(float4*)(op + 4) = o1;
}

// ---------------- launch ----------------
static cudaStream_t get_side_stream() {
    static cudaStream_t s = []() {
        cudaStream_t t;
        cudaStreamCreateWithFlags(&t, cudaStreamNonBlocking);
        return t;
    }();
    return s;
}
static cudaEvent_t get_ev(int which) {
    static cudaEvent_t e0 = []() {
        cudaEvent_t e;
        cudaEventCreateWithFlags(&e, cudaEventDisableTiming);
        return e;
    }();
    static cudaEvent_t e1 = []() {
        cudaEvent_t e;
        cudaEventCreateWithFlags(&e, cudaEventDisableTiming);
        return e;
    }();
    return which ? e1 : e0;
}

extern "C" void kernel_launch(void* const* d_in, const int* in_sizes, int n_in,
                              void* d_out, int out_size)
{
    const float *x, *ea, *Wl, *bl, *Wr, *br, *We, *att, *Wres, *bias, *gamma, *beta;
    const int* eidx;

    if (n_in >= 13 && in_sizes[2] == 2 * EN) {
        x     = (const float*)d_in[0];
        ea    = (const float*)d_in[1];
        eidx  = (const int*)  d_in[2];
        Wl    = (const float*)d_in[3];
        bl    = (const float*)d_in[4];
        Wr    = (const float*)d_in[5];
        br    = (const float*)d_in[6];
        We    = (const float*)d_in[7];
        att   = (const float*)d_in[8];
        Wres  = (const float*)d_in[9];
        bias  = (const float*)d_in[10];
        gamma = (const float*)d_in[11];
        beta  = (const float*)d_in[12];
    } else {
        x     = (const float*)d_in[0];
        ea    = (const float*)d_in[1];
        Wl    = (const float*)d_in[2];
        bl    = (const float*)d_in[3];
        Wr    = (const float*)d_in[4];
        br    = (const float*)d_in[5];
        We    = (const float*)d_in[6];
        att   = (const float*)d_in[7];
        Wres  = (const float*)d_in[8];
        bias  = (const float*)d_in[9];
        gamma = (const float*)d_in[10];
        beta  = (const float*)d_in[11];
        eidx  = (const int*)  d_in[12];
    }
    const int* esrc = eidx;
    const int* edst = eidx + EN;
    float* out = (float*)d_out;

    cudaFuncSetAttribute(node_gemm_tc, cudaFuncAttributeMaxDynamicSharedMemorySize, NODE_SMEM);
    cudaFuncSetAttribute(edge_kernel_tc, cudaFuncAttributeMaxDynamicSharedMemorySize, EDGE_SMEM);

    cudaStream_t s1 = get_side_stream();
    cudaEvent_t ev0 = get_ev(0), ev1 = get_ev(1);

    // fork: CSR build + We pack on side stream, node GEMM on main stream
    cudaEventRecord(ev0, 0);
    cudaStreamWaitEvent(s1, ev0, 0);

    pack_we_kernel<<<32, 256, 0, s1>>>(We);
    zero_kernel<<<(NN + 255) / 256, 256, 0, s1>>>();
    hist_kernel<<<(EN + 255) / 256, 256, 0, s1>>>(edst);
    scan_part<<<SCAN_BLOCKS, 256, 0, s1>>>();
    scan_mid<<<1, 256, 0, s1>>>();
    scan_final<<<SCAN_BLOCKS, 256, 0, s1>>>();
    fill_kernel<<<(EN + 255) / 256, 256, 0, s1>>>(esrc, edst);
    cudaEventRecord(ev1, s1);

    node_gemm_tc<<<dim3((NN + 127) / 128, 6), 256, NODE_SMEM>>>(x, Wl, bl, Wr, br, Wres, bias);

    // join
    cudaStreamWaitEvent(0, ev1, 0);
    edge_kernel_tc<<<EN / 128, 256, EDGE_SMEM>>>(ea, att);
    aggregate_ln_kernel<<<(NN + 7) / 8, 256>>>(gamma, beta, out);
}